// round 3
// baseline (speedup 1.0000x reference)
#include <cuda_runtime.h>
#include <cstdint>

#define NUM_NODES 50000
#define NUM_EDGES 50000
#define NNZ       500000
#define D_IN      256
#define D_OUT     256

// ---------------- static device scratch (no allocation allowed) ----------------
__device__ float g_xl[(size_t)NUM_NODES * D_OUT];      // x @ W
__device__ float g_efeat[(size_t)NUM_EDGES * D_OUT];   // per-hyperedge features
__device__ float g_D[NUM_NODES];                       // weighted node degree
__device__ int   g_ecnt[NUM_EDGES];                    // hyperedge cardinality
__device__ int   g_ncnt[NUM_NODES];                    // node incidence count
__device__ int   g_eptr[NUM_EDGES + 1];
__device__ int   g_nptr[NUM_NODES + 1];
__device__ int   g_efill[NUM_EDGES];
__device__ int   g_nfill[NUM_NODES];
__device__ int   g_enodes[NNZ];                        // CSR by edge: node ids
__device__ int   g_nedges[NNZ];                        // CSR by node: edge ids
__device__ int   g_nidx[NNZ];                          // decoded node index (int32)
__device__ int   g_eidx[NNZ];                          // decoded edge index (int32)
__device__ int   g_is64;                               // dtype flag

// ---------------- probe index dtype (int64 vs int32) ----------------
__global__ void probe_kernel(const unsigned int* __restrict__ buf) {
    // If data is int64 (values < 2^31), high words (odd uint32 indices) are 0.
    // If data is int32, odd words are random indices (almost never all zero).
    __shared__ int found_nonzero;
    if (threadIdx.x == 0) found_nonzero = 0;
    __syncthreads();
    // check 512 odd-position words
    for (int i = threadIdx.x; i < 512; i += blockDim.x) {
        if (buf[2 * i + 1] != 0u) atomicExch(&found_nonzero, 1);
    }
    __syncthreads();
    if (threadIdx.x == 0) g_is64 = found_nonzero ? 0 : 1;
}

// ---------------- decode indices to int32 ----------------
__global__ void decode_kernel(const void* __restrict__ buf) {
    int t = blockIdx.x * blockDim.x + threadIdx.x;
    if (t >= NNZ) return;
    int n, e;
    if (g_is64) {
        const long long* p = (const long long*)buf;
        n = (int)p[t];
        e = (int)p[NNZ + t];
    } else {
        const int* p = (const int*)buf;
        n = p[t];
        e = p[NNZ + t];
    }
    // clamp defensively (reference indices are in-range)
    if ((unsigned)n >= NUM_NODES) n = 0;
    if ((unsigned)e >= NUM_EDGES) e = 0;
    g_nidx[t] = n;
    g_eidx[t] = e;
}

// ---------------- zero counters ----------------
__global__ void zero_kernel() {
    int t = blockIdx.x * blockDim.x + threadIdx.x;
    if (t < NUM_NODES) { g_D[t] = 0.f; g_ncnt[t] = 0; g_nfill[t] = 0; }
    if (t < NUM_EDGES) { g_ecnt[t] = 0; g_efill[t] = 0; }
}

// ---------------- SGEMM: g_xl = x @ W  (fp32, 128x128x8 tiles) ----------------
#define BM 128
#define BN 128
#define BK 8
__global__ __launch_bounds__(256) void gemm_kernel(const float* __restrict__ A,
                                                   const float* __restrict__ B) {
    __shared__ float As[BK][BM];
    __shared__ float Bs[BK][BN];
    const int bm = blockIdx.y * BM;
    const int bn = blockIdx.x * BN;
    const int tid = threadIdx.x;
    const int tx = tid % 16;            // 16x16 thread grid, 8x8 regs each
    const int ty = tid / 16;

    float acc[8][8];
    #pragma unroll
    for (int i = 0; i < 8; i++)
        #pragma unroll
        for (int j = 0; j < 8; j++) acc[i][j] = 0.f;

    const int a_row  = tid >> 1;          // 0..127
    const int a_col4 = (tid & 1) * 4;     // 0 or 4
    const int b_row  = tid >> 5;          // 0..7
    const int b_col4 = (tid & 31) * 4;    // 0..124

    for (int k0 = 0; k0 < D_IN; k0 += BK) {
        float4 av = make_float4(0.f, 0.f, 0.f, 0.f);
        const int arow_g = bm + a_row;
        if (arow_g < NUM_NODES)
            av = *(const float4*)&A[(size_t)arow_g * D_IN + k0 + a_col4];
        As[a_col4 + 0][a_row] = av.x;
        As[a_col4 + 1][a_row] = av.y;
        As[a_col4 + 2][a_row] = av.z;
        As[a_col4 + 3][a_row] = av.w;
        *(float4*)&Bs[b_row][b_col4] =
            *(const float4*)&B[(size_t)(k0 + b_row) * D_OUT + bn + b_col4];
        __syncthreads();

        #pragma unroll
        for (int k = 0; k < BK; k++) {
            float ar[8], br[8];
            #pragma unroll
            for (int i = 0; i < 8; i++) ar[i] = As[k][ty * 8 + i];
            #pragma unroll
            for (int j = 0; j < 8; j++) br[j] = Bs[k][tx * 8 + j];
            #pragma unroll
            for (int i = 0; i < 8; i++)
                #pragma unroll
                for (int j = 0; j < 8; j++) acc[i][j] += ar[i] * br[j];
        }
        __syncthreads();
    }

    #pragma unroll
    for (int i = 0; i < 8; i++) {
        const int row = bm + ty * 8 + i;
        if (row < NUM_NODES) {
            #pragma unroll
            for (int j = 0; j < 8; j += 4) {
                *(float4*)&g_xl[(size_t)row * D_OUT + bn + tx * 8 + j] =
                    make_float4(acc[i][j], acc[i][j + 1], acc[i][j + 2], acc[i][j + 3]);
            }
        }
    }
}

// ---------------- histogram + weighted degree ----------------
__global__ void count_kernel(const float* __restrict__ w) {
    int t = blockIdx.x * blockDim.x + threadIdx.x;
    if (t >= NNZ) return;
    int n = g_nidx[t];
    int e = g_eidx[t];
    atomicAdd(&g_D[n], w[e]);
    atomicAdd(&g_ecnt[e], 1);
    atomicAdd(&g_ncnt[n], 1);
}

// ---------------- exclusive scan (grid = 2: edges, nodes) ----------------
__global__ __launch_bounds__(1024) void scan_kernel() {
    const int* cnt = (blockIdx.x == 0) ? g_ecnt : g_ncnt;
    int* ptr       = (blockIdx.x == 0) ? g_eptr : g_nptr;
    const int n    = (blockIdx.x == 0) ? NUM_EDGES : NUM_NODES;

    __shared__ int s[1024];
    __shared__ int carry;
    const int tid = threadIdx.x;
    if (tid == 0) carry = 0;
    __syncthreads();

    for (int base = 0; base < n; base += 1024) {
        const int i = base + tid;
        const int v = (i < n) ? cnt[i] : 0;
        s[tid] = v;
        __syncthreads();
        for (int off = 1; off < 1024; off <<= 1) {
            int t = (tid >= off) ? s[tid - off] : 0;
            __syncthreads();
            s[tid] += t;
            __syncthreads();
        }
        if (i < n) ptr[i] = carry + s[tid] - v;   // exclusive
        __syncthreads();
        if (tid == 0) carry += s[1023];
        __syncthreads();
    }
    if (tid == 0) ptr[n] = carry;
}

// ---------------- scatter nnz into both CSR structures ----------------
__global__ void scatter_kernel() {
    int t = blockIdx.x * blockDim.x + threadIdx.x;
    if (t >= NNZ) return;
    int n = g_nidx[t];
    int e = g_eidx[t];
    int p = g_eptr[e] + atomicAdd(&g_efill[e], 1);
    g_enodes[p] = n;
    int q = g_nptr[n] + atomicAdd(&g_nfill[n], 1);
    g_nedges[q] = e;
}

// ---------------- node -> hyperedge aggregation (atomic-free) ----------------
__global__ __launch_bounds__(D_OUT) void edge_agg_kernel() {
    const int e = blockIdx.x;
    const int f = threadIdx.x;
    const int beg = g_eptr[e];
    const int end = g_eptr[e + 1];
    __shared__ int sidx[D_OUT];
    float acc = 0.f;
    for (int base = beg; base < end; base += D_OUT) {
        const int cnt = min(D_OUT, end - base);
        if (f < cnt) sidx[f] = g_enodes[base + f];
        __syncthreads();
        for (int j = 0; j < cnt; j++)
            acc += g_xl[(size_t)sidx[j] * D_OUT + f];
        __syncthreads();
    }
    const float card = (float)(end - beg);
    const float binv = (card > 0.f) ? (1.f / card) : 0.f;
    g_efeat[(size_t)e * D_OUT + f] = acc * binv;
}

// ---------------- hyperedge -> node aggregation + bias ----------------
__global__ __launch_bounds__(D_OUT) void node_agg_kernel(float* __restrict__ out,
                                                         const float* __restrict__ b) {
    const int n = blockIdx.x;
    const int f = threadIdx.x;
    const int beg = g_nptr[n];
    const int end = g_nptr[n + 1];
    __shared__ int sidx[D_OUT];
    float acc = 0.f;
    for (int base = beg; base < end; base += D_OUT) {
        const int cnt = min(D_OUT, end - base);
        if (f < cnt) sidx[f] = g_nedges[base + f];
        __syncthreads();
        for (int j = 0; j < cnt; j++)
            acc += g_efeat[(size_t)sidx[j] * D_OUT + f];
        __syncthreads();
    }
    const float d = g_D[n];
    const float dinv = (d > 0.f) ? (1.f / d) : 0.f;
    out[(size_t)n * D_OUT + f] = acc * dinv + b[f];
}

// ---------------- launch ----------------
extern "C" void kernel_launch(void* const* d_in, const int* in_sizes, int n_in,
                              void* d_out, int out_size) {
    // Identify inputs by element count (all distinct) — robust to metadata order.
    const float* x  = nullptr;   // 12800000
    const void*  hi = nullptr;   // 1000000 (int32 or int64 — probed on device)
    const float* w  = nullptr;   // 50000
    const float* W  = nullptr;   // 65536
    const float* b  = nullptr;   // 256
    for (int i = 0; i < n_in; i++) {
        switch (in_sizes[i]) {
            case NUM_NODES * D_IN:   x  = (const float*)d_in[i]; break;
            case 2 * NNZ:            hi = d_in[i];               break;
            case NUM_EDGES:          w  = (const float*)d_in[i]; break;
            case D_IN * D_OUT:       W  = (const float*)d_in[i]; break;
            case D_OUT:              b  = (const float*)d_in[i]; break;
            default: break;
        }
    }
    float* out = (float*)d_out;

    probe_kernel<<<1, 256>>>((const unsigned int*)hi);
    decode_kernel<<<(NNZ + 255) / 256, 256>>>(hi);
    zero_kernel<<<(NUM_NODES + 255) / 256, 256>>>();

    dim3 ggrid(D_OUT / BN, (NUM_NODES + BM - 1) / BM);
    gemm_kernel<<<ggrid, 256>>>(x, W);

    count_kernel<<<(NNZ + 255) / 256, 256>>>(w);
    scan_kernel<<<2, 1024>>>();
    scatter_kernel<<<(NNZ + 255) / 256, 256>>>();

    edge_agg_kernel<<<NUM_EDGES, D_OUT>>>();
    node_agg_kernel<<<NUM_NODES, D_OUT>>>(out, b);
}

// round 4
// speedup vs baseline: 1.3777x; 1.3777x over previous
#include <cuda_runtime.h>
#include <cstdint>

#define NUM_NODES 50000
#define NUM_EDGES 50000
#define NNZ       500000
#define D_IN      256
#define D_OUT     256

// ---------------- static device scratch (no allocation allowed) ----------------
__device__ float g_xl[(size_t)NUM_NODES * D_OUT];      // x @ W
__device__ float g_efeat[(size_t)NUM_EDGES * D_OUT];   // per-hyperedge features
__device__ float g_D[NUM_NODES];                       // weighted node degree
__device__ int   g_ecnt[NUM_EDGES];                    // hyperedge cardinality
__device__ int   g_ncnt[NUM_NODES];                    // node incidence count
__device__ int   g_eptr[NUM_EDGES + 1];
__device__ int   g_nptr[NUM_NODES + 1];
__device__ int   g_efill[NUM_EDGES];
__device__ int   g_nfill[NUM_NODES];
__device__ int   g_enodes[NNZ];                        // CSR by edge: node ids
__device__ int   g_nedges[NNZ];                        // CSR by node: edge ids
__device__ int   g_nidx[NNZ];                          // decoded node index (int32)
__device__ int   g_eidx[NNZ];                          // decoded edge index (int32)
__device__ int   g_is64;                               // dtype flag

// ---------------- probe index dtype (int64 vs int32) ----------------
__global__ void probe_kernel(const unsigned int* __restrict__ buf) {
    __shared__ int found_nonzero;
    if (threadIdx.x == 0) found_nonzero = 0;
    __syncthreads();
    for (int i = threadIdx.x; i < 512; i += blockDim.x) {
        if (buf[2 * i + 1] != 0u) atomicExch(&found_nonzero, 1);
    }
    __syncthreads();
    if (threadIdx.x == 0) g_is64 = found_nonzero ? 0 : 1;
}

// ---------------- zero counters ----------------
__global__ void zero_kernel() {
    int t = blockIdx.x * blockDim.x + threadIdx.x;
    if (t < NUM_NODES) { g_D[t] = 0.f; g_ncnt[t] = 0; g_nfill[t] = 0; }
    if (t < NUM_EDGES) { g_ecnt[t] = 0; g_efill[t] = 0; }
}

// ---------------- decode indices + histogram + weighted degree (fused) --------
__global__ void decode_count_kernel(const void* __restrict__ buf,
                                    const float* __restrict__ w) {
    int t = blockIdx.x * blockDim.x + threadIdx.x;
    if (t >= NNZ) return;
    int n, e;
    if (g_is64) {
        const long long* p = (const long long*)buf;
        n = (int)p[t];
        e = (int)p[NNZ + t];
    } else {
        const int* p = (const int*)buf;
        n = p[t];
        e = p[NNZ + t];
    }
    if ((unsigned)n >= NUM_NODES) n = 0;
    if ((unsigned)e >= NUM_EDGES) e = 0;
    g_nidx[t] = n;
    g_eidx[t] = e;
    atomicAdd(&g_D[n], __ldg(&w[e]));
    atomicAdd(&g_ecnt[e], 1);
    atomicAdd(&g_ncnt[n], 1);
}

// ---------------- SGEMM: g_xl = x @ W  (fp32, 128x128x8, double-buffered) -----
#define BM 128
#define BN 128
#define BK 8
__global__ __launch_bounds__(256, 2) void gemm_kernel(const float* __restrict__ A,
                                                      const float* __restrict__ B) {
    __shared__ float As[2][BK][BM];
    __shared__ float Bs[2][BK][BN];
    const int bm = blockIdx.y * BM;
    const int bn = blockIdx.x * BN;
    const int tid = threadIdx.x;
    const int tx = tid % 16;
    const int ty = tid / 16;

    float acc[8][8];
    #pragma unroll
    for (int i = 0; i < 8; i++)
        #pragma unroll
        for (int j = 0; j < 8; j++) acc[i][j] = 0.f;

    const int a_row  = tid >> 1;
    const int a_col4 = (tid & 1) * 4;
    const int b_row  = tid >> 5;
    const int b_col4 = (tid & 31) * 4;
    const int arow_g = bm + a_row;
    const bool a_ok  = (arow_g < NUM_NODES);

    // prologue: load tile k0=0 into buffer 0
    float4 av = a_ok ? *(const float4*)&A[(size_t)arow_g * D_IN + a_col4]
                     : make_float4(0.f, 0.f, 0.f, 0.f);
    float4 bv = *(const float4*)&B[(size_t)b_row * D_OUT + bn + b_col4];
    As[0][a_col4 + 0][a_row] = av.x;
    As[0][a_col4 + 1][a_row] = av.y;
    As[0][a_col4 + 2][a_row] = av.z;
    As[0][a_col4 + 3][a_row] = av.w;
    *(float4*)&Bs[0][b_row][b_col4] = bv;
    __syncthreads();

    int buf = 0;
    for (int k0 = 0; k0 < D_IN; k0 += BK) {
        // prefetch next tile into registers
        const bool more = (k0 + BK < D_IN);
        if (more) {
            av = a_ok ? *(const float4*)&A[(size_t)arow_g * D_IN + k0 + BK + a_col4]
                      : make_float4(0.f, 0.f, 0.f, 0.f);
            bv = *(const float4*)&B[(size_t)(k0 + BK + b_row) * D_OUT + bn + b_col4];
        }
        // compute on current buffer
        #pragma unroll
        for (int k = 0; k < BK; k++) {
            float ar[8], br[8];
            #pragma unroll
            for (int i = 0; i < 8; i++) ar[i] = As[buf][k][ty * 8 + i];
            #pragma unroll
            for (int j = 0; j < 8; j++) br[j] = Bs[buf][k][tx * 8 + j];
            #pragma unroll
            for (int i = 0; i < 8; i++)
                #pragma unroll
                for (int j = 0; j < 8; j++) acc[i][j] += ar[i] * br[j];
        }
        // stage next tile into the alternate buffer
        if (more) {
            const int nb = buf ^ 1;
            As[nb][a_col4 + 0][a_row] = av.x;
            As[nb][a_col4 + 1][a_row] = av.y;
            As[nb][a_col4 + 2][a_row] = av.z;
            As[nb][a_col4 + 3][a_row] = av.w;
            *(float4*)&Bs[nb][b_row][b_col4] = bv;
            __syncthreads();
            buf = nb;
        }
    }

    #pragma unroll
    for (int i = 0; i < 8; i++) {
        const int row = bm + ty * 8 + i;
        if (row < NUM_NODES) {
            #pragma unroll
            for (int j = 0; j < 8; j += 4) {
                *(float4*)&g_xl[(size_t)row * D_OUT + bn + tx * 8 + j] =
                    make_float4(acc[i][j], acc[i][j + 1], acc[i][j + 2], acc[i][j + 3]);
            }
        }
    }
}

// ---------------- exclusive scan (2 blocks; thread-sequential + shuffle scan) --
__global__ __launch_bounds__(1024) void scan_kernel() {
    const int* cnt = (blockIdx.x == 0) ? g_ecnt : g_ncnt;
    int* ptr       = (blockIdx.x == 0) ? g_eptr : g_nptr;
    const int n    = (blockIdx.x == 0) ? NUM_EDGES : NUM_NODES;
    const int IPT  = (n + 1023) / 1024;

    const int t    = threadIdx.x;
    const int lane = t & 31;
    const int wid  = t >> 5;
    int beg = t * IPT; if (beg > n) beg = n;
    int end = beg + IPT; if (end > n) end = n;

    int sum = 0;
    for (int i = beg; i < end; i++) sum += cnt[i];

    // block-wide inclusive scan of per-thread sums
    int v = sum;
    #pragma unroll
    for (int o = 1; o < 32; o <<= 1) {
        int u = __shfl_up_sync(0xffffffffu, v, o);
        if (lane >= o) v += u;
    }
    __shared__ int warp_sums[32];
    if (lane == 31) warp_sums[wid] = v;
    __syncthreads();
    if (wid == 0) {
        int wv = warp_sums[lane];
        #pragma unroll
        for (int o = 1; o < 32; o <<= 1) {
            int u = __shfl_up_sync(0xffffffffu, wv, o);
            if (lane >= o) wv += u;
        }
        warp_sums[lane] = wv;
    }
    __syncthreads();
    int excl = v - sum + ((wid > 0) ? warp_sums[wid - 1] : 0);

    int run = excl;
    for (int i = beg; i < end; i++) { ptr[i] = run; run += cnt[i]; }
    if (t == 1023) ptr[n] = run;   // thread 1023's range is empty/last -> total
}

// ---------------- scatter nnz into both CSR structures ----------------
__global__ void scatter_kernel() {
    int t = blockIdx.x * blockDim.x + threadIdx.x;
    if (t >= NNZ) return;
    int n = g_nidx[t];
    int e = g_eidx[t];
    int p = g_eptr[e] + atomicAdd(&g_efill[e], 1);
    g_enodes[p] = n;
    int q = g_nptr[n] + atomicAdd(&g_nfill[n], 1);
    g_nedges[q] = e;
}

// ---------------- node -> hyperedge aggregation (float4, 64 lanes/segment) ----
__global__ __launch_bounds__(256) void edge_agg_kernel() {
    const int grp  = threadIdx.x >> 6;          // 0..3
    const int lane = threadIdx.x & 63;          // 0..63 (float4 lane)
    const int e = blockIdx.x * 4 + grp;
    if (e >= NUM_EDGES) return;
    const int beg = __ldg(&g_eptr[e]);
    const int end = __ldg(&g_eptr[e + 1]);
    const float4* __restrict__ xl4 = (const float4*)g_xl;

    float ax = 0.f, ay = 0.f, az = 0.f, aw = 0.f;
    int j = beg;
    for (; j + 2 <= end; j += 2) {
        const int i0 = __ldg(&g_enodes[j]);
        const int i1 = __ldg(&g_enodes[j + 1]);
        float4 a = __ldg(&xl4[(size_t)i0 * 64 + lane]);
        float4 c = __ldg(&xl4[(size_t)i1 * 64 + lane]);
        ax += a.x + c.x; ay += a.y + c.y; az += a.z + c.z; aw += a.w + c.w;
    }
    if (j < end) {
        const int i0 = __ldg(&g_enodes[j]);
        float4 a = __ldg(&xl4[(size_t)i0 * 64 + lane]);
        ax += a.x; ay += a.y; az += a.z; aw += a.w;
    }
    const float card = (float)(end - beg);
    const float binv = (card > 0.f) ? (1.f / card) : 0.f;
    ((float4*)g_efeat)[(size_t)e * 64 + lane] =
        make_float4(ax * binv, ay * binv, az * binv, aw * binv);
}

// ---------------- hyperedge -> node aggregation + bias ----------------
__global__ __launch_bounds__(256) void node_agg_kernel(float* __restrict__ out,
                                                       const float* __restrict__ b) {
    const int grp  = threadIdx.x >> 6;
    const int lane = threadIdx.x & 63;
    const int n = blockIdx.x * 4 + grp;
    if (n >= NUM_NODES) return;
    const int beg = __ldg(&g_nptr[n]);
    const int end = __ldg(&g_nptr[n + 1]);
    const float4* __restrict__ ef4 = (const float4*)g_efeat;

    float ax = 0.f, ay = 0.f, az = 0.f, aw = 0.f;
    int j = beg;
    for (; j + 2 <= end; j += 2) {
        const int e0 = __ldg(&g_nedges[j]);
        const int e1 = __ldg(&g_nedges[j + 1]);
        float4 a = __ldg(&ef4[(size_t)e0 * 64 + lane]);
        float4 c = __ldg(&ef4[(size_t)e1 * 64 + lane]);
        ax += a.x + c.x; ay += a.y + c.y; az += a.z + c.z; aw += a.w + c.w;
    }
    if (j < end) {
        const int e0 = __ldg(&g_nedges[j]);
        float4 a = __ldg(&ef4[(size_t)e0 * 64 + lane]);
        ax += a.x; ay += a.y; az += a.z; aw += a.w;
    }
    const float d = __ldg(&g_D[n]);
    const float dinv = (d > 0.f) ? (1.f / d) : 0.f;
    const float4 bb = __ldg(&((const float4*)b)[lane]);
    ((float4*)out)[(size_t)n * 64 + lane] =
        make_float4(ax * dinv + bb.x, ay * dinv + bb.y,
                    az * dinv + bb.z, aw * dinv + bb.w);
}

// ---------------- launch ----------------
extern "C" void kernel_launch(void* const* d_in, const int* in_sizes, int n_in,
                              void* d_out, int out_size) {
    const float* x  = nullptr;   // 12800000
    const void*  hi = nullptr;   // 1000000 (int32 or int64 — probed on device)
    const float* w  = nullptr;   // 50000
    const float* W  = nullptr;   // 65536
    const float* b  = nullptr;   // 256
    for (int i = 0; i < n_in; i++) {
        switch (in_sizes[i]) {
            case NUM_NODES * D_IN:   x  = (const float*)d_in[i]; break;
            case 2 * NNZ:            hi = d_in[i];               break;
            case NUM_EDGES:          w  = (const float*)d_in[i]; break;
            case D_IN * D_OUT:       W  = (const float*)d_in[i]; break;
            case D_OUT:              b  = (const float*)d_in[i]; break;
            default: break;
        }
    }
    float* out = (float*)d_out;

    probe_kernel<<<1, 256>>>((const unsigned int*)hi);
    zero_kernel<<<(NUM_NODES + 255) / 256, 256>>>();
    decode_count_kernel<<<(NNZ + 255) / 256, 256>>>(hi, w);

    dim3 ggrid(D_OUT / BN, (NUM_NODES + BM - 1) / BM);
    gemm_kernel<<<ggrid, 256>>>(x, W);

    scan_kernel<<<2, 1024>>>();
    scatter_kernel<<<(NNZ + 255) / 256, 256>>>();

    edge_agg_kernel<<<(NUM_EDGES + 3) / 4, 256>>>();
    node_agg_kernel<<<(NUM_NODES + 3) / 4, 256>>>(out, b);
}

// round 7
// speedup vs baseline: 1.8811x; 1.3655x over previous
#include <cuda_runtime.h>
#include <cuda_bf16.h>
#include <cstdint>

#define NUM_NODES 50000
#define NUM_EDGES 50000
#define NNZ       500000
#define D_IN      256
#define D_OUT     256

// ---------------- static device scratch (no allocation allowed) ----------------
__device__ float g_xl[(size_t)NUM_NODES * D_OUT];      // x @ W
__device__ float g_efeat[(size_t)NUM_EDGES * D_OUT];   // per-hyperedge features
__device__ float g_D[NUM_NODES];
__device__ int   g_ecnt[NUM_EDGES];
__device__ int   g_ncnt[NUM_NODES];
__device__ int   g_eptr[NUM_EDGES + 1];
__device__ int   g_nptr[NUM_NODES + 1];
__device__ int   g_efill[NUM_EDGES];
__device__ int   g_nfill[NUM_NODES];
__device__ int   g_enodes[NNZ];
__device__ int   g_nedges[NNZ];
__device__ int   g_nidx[NNZ];
__device__ int   g_eidx[NNZ];
__device__ int   g_is64;
// split-bf16 operands for HMMA GEMM
__device__ __nv_bfloat16 g_xhi[(size_t)NUM_NODES * D_IN];
__device__ __nv_bfloat16 g_xlo[(size_t)NUM_NODES * D_IN];
__device__ __nv_bfloat16 g_whi[D_IN * D_OUT];          // stored [N][K] (K-major)
__device__ __nv_bfloat16 g_wlo[D_IN * D_OUT];

// ---------------- helpers ----------------
__device__ __forceinline__ uint32_t smem_to_u32(const void* p) {
    uint32_t a;
    asm("{ .reg .u64 t; cvta.to.shared.u64 t, %1; cvt.u32.u64 %0, t; }" : "=r"(a) : "l"(p));
    return a;
}
#define LDMATRIX_X4(r, addr) \
    asm volatile("ldmatrix.sync.aligned.m8n8.x4.shared.b16 {%0,%1,%2,%3}, [%4];" \
                 : "=r"((r)[0]), "=r"((r)[1]), "=r"((r)[2]), "=r"((r)[3]) : "r"(addr))
__device__ __forceinline__ void mma16816(float* d, const uint32_t* a, const uint32_t* b) {
    asm volatile("mma.sync.aligned.m16n8k16.row.col.f32.bf16.bf16.f32 "
                 "{%0,%1,%2,%3}, {%4,%5,%6,%7}, {%8,%9}, {%0,%1,%2,%3};"
                 : "+f"(d[0]), "+f"(d[1]), "+f"(d[2]), "+f"(d[3])
                 : "r"(a[0]), "r"(a[1]), "r"(a[2]), "r"(a[3]), "r"(b[0]), "r"(b[1]));
}

// ---------------- probe index dtype (int64 vs int32) ----------------
__global__ void probe_kernel(const unsigned int* __restrict__ buf) {
    __shared__ int found_nonzero;
    if (threadIdx.x == 0) found_nonzero = 0;
    __syncthreads();
    for (int i = threadIdx.x; i < 512; i += blockDim.x)
        if (buf[2 * i + 1] != 0u) atomicExch(&found_nonzero, 1);
    __syncthreads();
    if (threadIdx.x == 0) g_is64 = found_nonzero ? 0 : 1;
}

// ---------------- zero counters ----------------
__global__ void zero_kernel() {
    int t = blockIdx.x * blockDim.x + threadIdx.x;
    if (t < NUM_NODES) { g_D[t] = 0.f; g_ncnt[t] = 0; g_nfill[t] = 0; }
    if (t < NUM_EDGES) { g_ecnt[t] = 0; g_efill[t] = 0; }
}

// ---------------- decode indices + histogram + weighted degree (fused) --------
__global__ void decode_count_kernel(const void* __restrict__ buf,
                                    const float* __restrict__ w) {
    int t = blockIdx.x * blockDim.x + threadIdx.x;
    if (t >= NNZ) return;
    int n, e;
    if (g_is64) {
        const long long* p = (const long long*)buf;
        n = (int)p[t];
        e = (int)p[NNZ + t];
    } else {
        const int* p = (const int*)buf;
        n = p[t];
        e = p[NNZ + t];
    }
    if ((unsigned)n >= NUM_NODES) n = 0;
    if ((unsigned)e >= NUM_EDGES) e = 0;
    g_nidx[t] = n;
    g_eidx[t] = e;
    atomicAdd(&g_D[n], __ldg(&w[e]));
    atomicAdd(&g_ecnt[e], 1);
    atomicAdd(&g_ncnt[n], 1);
}

// ---------------- split fp32 -> bf16 hi/lo ----------------
__global__ void split_x_kernel(const float* __restrict__ x) {
    int t = blockIdx.x * blockDim.x + threadIdx.x;
    const int n4 = NUM_NODES * D_IN / 4;
    if (t >= n4) return;
    float4 v = __ldg(&((const float4*)x)[t]);
    __nv_bfloat16 h0 = __float2bfloat16_rn(v.x), h1 = __float2bfloat16_rn(v.y);
    __nv_bfloat16 h2 = __float2bfloat16_rn(v.z), h3 = __float2bfloat16_rn(v.w);
    __nv_bfloat16 l0 = __float2bfloat16_rn(v.x - __bfloat162float(h0));
    __nv_bfloat16 l1 = __float2bfloat16_rn(v.y - __bfloat162float(h1));
    __nv_bfloat16 l2 = __float2bfloat16_rn(v.z - __bfloat162float(h2));
    __nv_bfloat16 l3 = __float2bfloat16_rn(v.w - __bfloat162float(h3));
    ((__nv_bfloat162*)g_xhi)[2 * t]     = __halves2bfloat162(h0, h1);
    ((__nv_bfloat162*)g_xhi)[2 * t + 1] = __halves2bfloat162(h2, h3);
    ((__nv_bfloat162*)g_xlo)[2 * t]     = __halves2bfloat162(l0, l1);
    ((__nv_bfloat162*)g_xlo)[2 * t + 1] = __halves2bfloat162(l2, l3);
}
// W[k][n] -> w_hi/w_lo stored [n][k] (K-major B for row.col mma)
__global__ void split_w_kernel(const float* __restrict__ W) {
    int t = blockIdx.x * blockDim.x + threadIdx.x;
    if (t >= D_IN * D_OUT) return;
    int n = t >> 8, k = t & 255;
    float v = __ldg(&W[k * D_OUT + n]);
    __nv_bfloat16 h = __float2bfloat16_rn(v);
    g_whi[n * D_IN + k] = h;
    g_wlo[n * D_IN + k] = __float2bfloat16_rn(v - __bfloat162float(h));
}

// ---------------- HMMA split-bf16 GEMM: g_xl = x @ W ----------------
// CTA 128x128, 8 warps (4x2), warp tile 32x64, K chunks of 32.
// smem rows padded to 40 halves (80B) -> conflict-free ldmatrix.
#define SPAD 40
__global__ __launch_bounds__(256, 2) void mma_gemm_kernel() {
    __shared__ __nv_bfloat16 As_hi[128][SPAD], As_lo[128][SPAD];
    __shared__ __nv_bfloat16 Bs_hi[128][SPAD], Bs_lo[128][SPAD];

    const int tid  = threadIdx.x;
    const int lane = tid & 31;
    const int wid  = tid >> 5;
    const int wm   = (wid >> 1) * 32;      // warp row offset in CTA tile
    const int wn   = (wid & 1) * 64;       // warp col offset
    const int m0   = blockIdx.y * 128;
    const int n0   = blockIdx.x * 128;

    float acc[2][8][4];
    #pragma unroll
    for (int i = 0; i < 2; i++)
        #pragma unroll
        for (int j = 0; j < 8; j++)
            #pragma unroll
            for (int q = 0; q < 4; q++) acc[i][j][q] = 0.f;

    const uint32_t a_hi_b = smem_to_u32(&As_hi[0][0]);
    const uint32_t a_lo_b = smem_to_u32(&As_lo[0][0]);
    const uint32_t b_hi_b = smem_to_u32(&Bs_hi[0][0]);
    const uint32_t b_lo_b = smem_to_u32(&Bs_lo[0][0]);

    for (int kc = 0; kc < 8; kc++) {
        const int k0 = kc * 32;
        __syncthreads();
        // load 128 rows x 32 halves for each of the 4 operands
        #pragma unroll
        for (int i = tid; i < 512; i += 256) {
            const int r = i >> 2, seg = i & 3;     // seg: 16B (8 halves)
            const int gr = m0 + r;
            uint4 vh = make_uint4(0, 0, 0, 0), vl = vh;
            if (gr < NUM_NODES) {
                vh = *(const uint4*)(g_xhi + (size_t)gr * D_IN + k0 + seg * 8);
                vl = *(const uint4*)(g_xlo + (size_t)gr * D_IN + k0 + seg * 8);
            }
            *(uint4*)&As_hi[r][seg * 8] = vh;
            *(uint4*)&As_lo[r][seg * 8] = vl;
            const int gn = n0 + r;
            *(uint4*)&Bs_hi[r][seg * 8] = *(const uint4*)(g_whi + (size_t)gn * D_IN + k0 + seg * 8);
            *(uint4*)&Bs_lo[r][seg * 8] = *(const uint4*)(g_wlo + (size_t)gn * D_IN + k0 + seg * 8);
        }
        __syncthreads();

        #pragma unroll
        for (int kk = 0; kk < 32; kk += 16) {
            uint32_t ah[2][4], al[2][4];
            #pragma unroll
            for (int ti = 0; ti < 2; ti++) {
                const int row = wm + ti * 16 + (lane & 15);
                const uint32_t off = (uint32_t)(row * (SPAD * 2) + (kk + (lane >> 4) * 8) * 2);
                LDMATRIX_X4(ah[ti], a_hi_b + off);
                LDMATRIX_X4(al[ti], a_lo_b + off);
            }
            uint32_t bh[8][2], bl[8][2];
            #pragma unroll
            for (int tj = 0; tj < 4; tj++) {
                const int row = wn + tj * 16 + (lane & 15);
                const uint32_t off = (uint32_t)(row * (SPAD * 2) + (kk + (lane >> 4) * 8) * 2);
                uint32_t r4[4];
                LDMATRIX_X4(r4, b_hi_b + off);
                bh[2 * tj][0] = r4[0]; bh[2 * tj + 1][0] = r4[1];
                bh[2 * tj][1] = r4[2]; bh[2 * tj + 1][1] = r4[3];
                LDMATRIX_X4(r4, b_lo_b + off);
                bl[2 * tj][0] = r4[0]; bl[2 * tj + 1][0] = r4[1];
                bl[2 * tj][1] = r4[2]; bl[2 * tj + 1][1] = r4[3];
            }
            #pragma unroll
            for (int ti = 0; ti < 2; ti++)
                #pragma unroll
                for (int j = 0; j < 8; j++) {
                    mma16816(acc[ti][j], ah[ti], bh[j]);   // hi*hi
                    mma16816(acc[ti][j], ah[ti], bl[j]);   // hi*lo
                    mma16816(acc[ti][j], al[ti], bh[j]);   // lo*hi
                }
        }
    }

    // epilogue: d0,d1 -> (row, col..col+1); d2,d3 -> (row+8, ...)
    #pragma unroll
    for (int ti = 0; ti < 2; ti++) {
        const int r0 = m0 + wm + ti * 16 + (lane >> 2);
        #pragma unroll
        for (int j = 0; j < 8; j++) {
            const int c = n0 + wn + j * 8 + (lane & 3) * 2;
            if (r0 < NUM_NODES)
                *(float2*)&g_xl[(size_t)r0 * D_OUT + c] = make_float2(acc[ti][j][0], acc[ti][j][1]);
            if (r0 + 8 < NUM_NODES)
                *(float2*)&g_xl[(size_t)(r0 + 8) * D_OUT + c] = make_float2(acc[ti][j][2], acc[ti][j][3]);
        }
    }
}

// ---------------- exclusive scan (2 blocks; thread-sequential + shuffle scan) --
__global__ __launch_bounds__(1024) void scan_kernel() {
    const int* cnt = (blockIdx.x == 0) ? g_ecnt : g_ncnt;
    int* ptr       = (blockIdx.x == 0) ? g_eptr : g_nptr;
    const int n    = (blockIdx.x == 0) ? NUM_EDGES : NUM_NODES;
    const int IPT  = (n + 1023) / 1024;

    const int t    = threadIdx.x;
    const int lane = t & 31;
    const int wid  = t >> 5;
    int beg = t * IPT; if (beg > n) beg = n;
    int end = beg + IPT; if (end > n) end = n;

    int sum = 0;
    for (int i = beg; i < end; i++) sum += cnt[i];

    int v = sum;
    #pragma unroll
    for (int o = 1; o < 32; o <<= 1) {
        int u = __shfl_up_sync(0xffffffffu, v, o);
        if (lane >= o) v += u;
    }
    __shared__ int warp_sums[32];
    if (lane == 31) warp_sums[wid] = v;
    __syncthreads();
    if (wid == 0) {
        int wv = warp_sums[lane];
        #pragma unroll
        for (int o = 1; o < 32; o <<= 1) {
            int u = __shfl_up_sync(0xffffffffu, wv, o);
            if (lane >= o) wv += u;
        }
        warp_sums[lane] = wv;
    }
    __syncthreads();
    int excl = v - sum + ((wid > 0) ? warp_sums[wid - 1] : 0);

    int run = excl;
    for (int i = beg; i < end; i++) { ptr[i] = run; run += cnt[i]; }
    if (t == 1023) ptr[n] = run;
}

// ---------------- scatter nnz into both CSR structures ----------------
__global__ void scatter_kernel() {
    int t = blockIdx.x * blockDim.x + threadIdx.x;
    if (t >= NNZ) return;
    int n = g_nidx[t];
    int e = g_eidx[t];
    int p = g_eptr[e] + atomicAdd(&g_efill[e], 1);
    g_enodes[p] = n;
    int q = g_nptr[n] + atomicAdd(&g_nfill[n], 1);
    g_nedges[q] = e;
}

// ---------------- node -> hyperedge aggregation (float4, 64 lanes/segment) ----
__global__ __launch_bounds__(256) void edge_agg_kernel() {
    const int grp  = threadIdx.x >> 6;
    const int lane = threadIdx.x & 63;
    const int e = blockIdx.x * 4 + grp;
    if (e >= NUM_EDGES) return;
    const int beg = __ldg(&g_eptr[e]);
    const int end = __ldg(&g_eptr[e + 1]);
    const float4* __restrict__ xl4 = (const float4*)g_xl;

    float ax = 0.f, ay = 0.f, az = 0.f, aw = 0.f;
    int j = beg;
    for (; j + 2 <= end; j += 2) {
        const int i0 = __ldg(&g_enodes[j]);
        const int i1 = __ldg(&g_enodes[j + 1]);
        float4 a = __ldg(&xl4[(size_t)i0 * 64 + lane]);
        float4 c = __ldg(&xl4[(size_t)i1 * 64 + lane]);
        ax += a.x + c.x; ay += a.y + c.y; az += a.z + c.z; aw += a.w + c.w;
    }
    if (j < end) {
        const int i0 = __ldg(&g_enodes[j]);
        float4 a = __ldg(&xl4[(size_t)i0 * 64 + lane]);
        ax += a.x; ay += a.y; az += a.z; aw += a.w;
    }
    const float card = (float)(end - beg);
    const float binv = (card > 0.f) ? (1.f / card) : 0.f;
    ((float4*)g_efeat)[(size_t)e * 64 + lane] =
        make_float4(ax * binv, ay * binv, az * binv, aw * binv);
}

// ---------------- hyperedge -> node aggregation + bias ----------------
__global__ __launch_bounds__(256) void node_agg_kernel(float* __restrict__ out,
                                                       const float* __restrict__ b) {
    const int grp  = threadIdx.x >> 6;
    const int lane = threadIdx.x & 63;
    const int n = blockIdx.x * 4 + grp;
    if (n >= NUM_NODES) return;
    const int beg = __ldg(&g_nptr[n]);
    const int end = __ldg(&g_nptr[n + 1]);
    const float4* __restrict__ ef4 = (const float4*)g_efeat;

    float ax = 0.f, ay = 0.f, az = 0.f, aw = 0.f;
    int j = beg;
    for (; j + 2 <= end; j += 2) {
        const int e0 = __ldg(&g_nedges[j]);
        const int e1 = __ldg(&g_nedges[j + 1]);
        float4 a = __ldg(&ef4[(size_t)e0 * 64 + lane]);
        float4 c = __ldg(&ef4[(size_t)e1 * 64 + lane]);
        ax += a.x + c.x; ay += a.y + c.y; az += a.z + c.z; aw += a.w + c.w;
    }
    if (j < end) {
        const int e0 = __ldg(&g_nedges[j]);
        float4 a = __ldg(&ef4[(size_t)e0 * 64 + lane]);
        ax += a.x; ay += a.y; az += a.z; aw += a.w;
    }
    const float d = __ldg(&g_D[n]);
    const float dinv = (d > 0.f) ? (1.f / d) : 0.f;
    const float4 bb = __ldg(&((const float4*)b)[lane]);
    ((float4*)out)[(size_t)n * 64 + lane] =
        make_float4(ax * dinv + bb.x, ay * dinv + bb.y,
                    az * dinv + bb.z, aw * dinv + bb.w);
}

// ---------------- launch ----------------
extern "C" void kernel_launch(void* const* d_in, const int* in_sizes, int n_in,
                              void* d_out, int out_size) {
    const float* x  = nullptr;
    const void*  hi = nullptr;
    const float* w  = nullptr;
    const float* W  = nullptr;
    const float* b  = nullptr;
    for (int i = 0; i < n_in; i++) {
        switch (in_sizes[i]) {
            case NUM_NODES * D_IN:   x  = (const float*)d_in[i]; break;
            case 2 * NNZ:            hi = d_in[i];               break;
            case NUM_EDGES:          w  = (const float*)d_in[i]; break;
            case D_IN * D_OUT:       W  = (const float*)d_in[i]; break;
            case D_OUT:              b  = (const float*)d_in[i]; break;
            default: break;
        }
    }
    float* out = (float*)d_out;

    probe_kernel<<<1, 256>>>((const unsigned int*)hi);
    zero_kernel<<<(NUM_NODES + 255) / 256, 256>>>();
    decode_count_kernel<<<(NNZ + 255) / 256, 256>>>(hi, w);

    split_x_kernel<<<(NUM_NODES * D_IN / 4 + 255) / 256, 256>>>(x);
    split_w_kernel<<<(D_IN * D_OUT + 255) / 256, 256>>>(W);

    dim3 ggrid(D_OUT / 128, (NUM_NODES + 127) / 128);
    mma_gemm_kernel<<<ggrid, 256>>>();

    scan_kernel<<<2, 1024>>>();
    scatter_kernel<<<(NNZ + 255) / 256, 256>>>();

    edge_agg_kernel<<<(NUM_EDGES + 3) / 4, 256>>>();
    node_agg_kernel<<<(NUM_NODES + 3) / 4, 256>>>(out, b);
}

// round 9
// speedup vs baseline: 2.0624x; 1.0963x over previous
#include <cuda_runtime.h>
#include <cuda_bf16.h>
#include <cstdint>

#define NUM_NODES 50000
#define NUM_EDGES 50000
#define NNZ       500000
#define D_IN      256
#define D_OUT     256

// ---------------- static device scratch (no allocation allowed) ----------------
__device__ float g_xl[(size_t)NUM_NODES * D_OUT];      // x @ W
__device__ float g_efeat[(size_t)NUM_EDGES * D_OUT];   // per-hyperedge features
__device__ float g_D[NUM_NODES];
__device__ int   g_ecnt[NUM_EDGES];
__device__ int   g_ncnt[NUM_NODES];
__device__ int   g_eptr[NUM_EDGES + 1];
__device__ int   g_nptr[NUM_NODES + 1];
__device__ int   g_efill[NUM_EDGES];
__device__ int   g_nfill[NUM_NODES];
__device__ int   g_enodes[NNZ];
__device__ int   g_nedges[NNZ];
__device__ int   g_nidx[NNZ];
__device__ int   g_eidx[NNZ];
__device__ int   g_is64;
// split-bf16 W for HMMA GEMM (x is converted in-kernel)
__device__ __nv_bfloat16 g_whi[D_IN * D_OUT];          // stored [N][K] (K-major)
__device__ __nv_bfloat16 g_wlo[D_IN * D_OUT];

// ---------------- helpers ----------------
__device__ __forceinline__ uint32_t smem_to_u32(const void* p) {
    uint32_t a;
    asm("{ .reg .u64 t; cvta.to.shared.u64 t, %1; cvt.u32.u64 %0, t; }" : "=r"(a) : "l"(p));
    return a;
}
#define LDMATRIX_X4(r, addr) \
    asm volatile("ldmatrix.sync.aligned.m8n8.x4.shared.b16 {%0,%1,%2,%3}, [%4];" \
                 : "=r"((r)[0]), "=r"((r)[1]), "=r"((r)[2]), "=r"((r)[3]) : "r"(addr))
__device__ __forceinline__ void mma16816(float* d, const uint32_t* a, const uint32_t* b) {
    asm volatile("mma.sync.aligned.m16n8k16.row.col.f32.bf16.bf16.f32 "
                 "{%0,%1,%2,%3}, {%4,%5,%6,%7}, {%8,%9}, {%0,%1,%2,%3};"
                 : "+f"(d[0]), "+f"(d[1]), "+f"(d[2]), "+f"(d[3])
                 : "r"(a[0]), "r"(a[1]), "r"(a[2]), "r"(a[3]), "r"(b[0]), "r"(b[1]));
}
// 4 fp32 -> 2 packed bf16x2 (hi) + 2 packed bf16x2 (lo residual)
__device__ __forceinline__ void cvt4(const float4 v, uint32_t* hi2, uint32_t* lo2) {
    __nv_bfloat16 h0 = __float2bfloat16_rn(v.x), h1 = __float2bfloat16_rn(v.y);
    __nv_bfloat16 h2 = __float2bfloat16_rn(v.z), h3 = __float2bfloat16_rn(v.w);
    __nv_bfloat162 H0 = __halves2bfloat162(h0, h1);
    __nv_bfloat162 H1 = __halves2bfloat162(h2, h3);
    __nv_bfloat162 L0 = __halves2bfloat162(__float2bfloat16_rn(v.x - __bfloat162float(h0)),
                                           __float2bfloat16_rn(v.y - __bfloat162float(h1)));
    __nv_bfloat162 L1 = __halves2bfloat162(__float2bfloat16_rn(v.z - __bfloat162float(h2)),
                                           __float2bfloat16_rn(v.w - __bfloat162float(h3)));
    hi2[0] = *(uint32_t*)&H0; hi2[1] = *(uint32_t*)&H1;
    lo2[0] = *(uint32_t*)&L0; lo2[1] = *(uint32_t*)&L1;
}

// ---------------- probe index dtype (int64 vs int32) ----------------
__global__ void probe_kernel(const unsigned int* __restrict__ buf) {
    __shared__ int found_nonzero;
    if (threadIdx.x == 0) found_nonzero = 0;
    __syncthreads();
    for (int i = threadIdx.x; i < 512; i += blockDim.x)
        if (buf[2 * i + 1] != 0u) atomicExch(&found_nonzero, 1);
    __syncthreads();
    if (threadIdx.x == 0) g_is64 = found_nonzero ? 0 : 1;
}

// ---------------- zero counters ----------------
__global__ void zero_kernel() {
    int t = blockIdx.x * blockDim.x + threadIdx.x;
    if (t < NUM_NODES) { g_D[t] = 0.f; g_ncnt[t] = 0; g_nfill[t] = 0; }
    if (t < NUM_EDGES) { g_ecnt[t] = 0; g_efill[t] = 0; }
}

// ---------------- decode indices + histogram + weighted degree (fused) --------
__global__ void decode_count_kernel(const void* __restrict__ buf,
                                    const float* __restrict__ w) {
    int t = blockIdx.x * blockDim.x + threadIdx.x;
    if (t >= NNZ) return;
    int n, e;
    if (g_is64) {
        const long long* p = (const long long*)buf;
        n = (int)p[t];
        e = (int)p[NNZ + t];
    } else {
        const int* p = (const int*)buf;
        n = p[t];
        e = p[NNZ + t];
    }
    if ((unsigned)n >= NUM_NODES) n = 0;
    if ((unsigned)e >= NUM_EDGES) e = 0;
    g_nidx[t] = n;
    g_eidx[t] = e;
    atomicAdd(&g_D[n], __ldg(&w[e]));
    atomicAdd(&g_ecnt[e], 1);
    atomicAdd(&g_ncnt[n], 1);
}

// W[k][n] -> w_hi/w_lo stored [n][k] (K-major B for row.col mma)
__global__ void split_w_kernel(const float* __restrict__ W) {
    int t = blockIdx.x * blockDim.x + threadIdx.x;
    if (t >= D_IN * D_OUT) return;
    int n = t >> 8, k = t & 255;
    float v = __ldg(&W[k * D_OUT + n]);
    __nv_bfloat16 h = __float2bfloat16_rn(v);
    g_whi[n * D_IN + k] = h;
    g_wlo[n * D_IN + k] = __float2bfloat16_rn(v - __bfloat162float(h));
}

// ---------------- HMMA split-bf16 GEMM: g_xl = x @ W (fused fp32->hi/lo) ------
// CTA 128x128, 8 warps (4x2), warp tile 32x64, K chunks of 32.
// smem rows padded to 40 halves (80B) -> conflict-free ldmatrix.
#define SPAD 40
__global__ __launch_bounds__(256, 2) void mma_gemm_kernel(const float* __restrict__ X) {
    __shared__ __nv_bfloat16 As_hi[128][SPAD], As_lo[128][SPAD];
    __shared__ __nv_bfloat16 Bs_hi[128][SPAD], Bs_lo[128][SPAD];

    const int tid  = threadIdx.x;
    const int lane = tid & 31;
    const int wid  = tid >> 5;
    const int wm   = (wid >> 1) * 32;      // warp row offset in CTA tile
    const int wn   = (wid & 1) * 64;       // warp col offset
    const int m0   = blockIdx.y * 128;
    const int n0   = blockIdx.x * 128;

    float acc[2][8][4];
    #pragma unroll
    for (int i = 0; i < 2; i++)
        #pragma unroll
        for (int j = 0; j < 8; j++)
            #pragma unroll
            for (int q = 0; q < 4; q++) acc[i][j][q] = 0.f;

    const uint32_t a_hi_b = smem_to_u32(&As_hi[0][0]);
    const uint32_t a_lo_b = smem_to_u32(&As_lo[0][0]);
    const uint32_t b_hi_b = smem_to_u32(&Bs_hi[0][0]);
    const uint32_t b_lo_b = smem_to_u32(&Bs_lo[0][0]);

    for (int kc = 0; kc < 8; kc++) {
        const int k0 = kc * 32;
        __syncthreads();
        // A: 128 rows x 32 fp32 -> convert to hi/lo bf16 while staging
        #pragma unroll
        for (int i = tid; i < 512; i += 256) {
            const int r = i >> 2, seg = i & 3;     // seg: 8 floats
            const int gr = m0 + r;
            float4 v0 = make_float4(0.f, 0.f, 0.f, 0.f), v1 = v0;
            if (gr < NUM_NODES) {
                const float* src = X + (size_t)gr * D_IN + k0 + seg * 8;
                v0 = __ldg((const float4*)src);
                v1 = __ldg((const float4*)(src + 4));
            }
            uint32_t hi[4], lo[4];
            cvt4(v0, hi, lo);
            cvt4(v1, hi + 2, lo + 2);
            *(uint4*)&As_hi[r][seg * 8] = make_uint4(hi[0], hi[1], hi[2], hi[3]);
            *(uint4*)&As_lo[r][seg * 8] = make_uint4(lo[0], lo[1], lo[2], lo[3]);
            const int gn = n0 + r;
            *(uint4*)&Bs_hi[r][seg * 8] = *(const uint4*)(g_whi + (size_t)gn * D_IN + k0 + seg * 8);
            *(uint4*)&Bs_lo[r][seg * 8] = *(const uint4*)(g_wlo + (size_t)gn * D_IN + k0 + seg * 8);
        }
        __syncthreads();

        #pragma unroll
        for (int kk = 0; kk < 32; kk += 16) {
            uint32_t ah[2][4], al[2][4];
            #pragma unroll
            for (int ti = 0; ti < 2; ti++) {
                const int row = wm + ti * 16 + (lane & 15);
                const uint32_t off = (uint32_t)(row * (SPAD * 2) + (kk + (lane >> 4) * 8) * 2);
                LDMATRIX_X4(ah[ti], a_hi_b + off);
                LDMATRIX_X4(al[ti], a_lo_b + off);
            }
            uint32_t bh[8][2], bl[8][2];
            #pragma unroll
            for (int tj = 0; tj < 4; tj++) {
                const int row = wn + tj * 16 + (lane & 15);
                const uint32_t off = (uint32_t)(row * (SPAD * 2) + (kk + (lane >> 4) * 8) * 2);
                uint32_t r4[4];
                LDMATRIX_X4(r4, b_hi_b + off);
                bh[2 * tj][0] = r4[0]; bh[2 * tj + 1][0] = r4[1];
                bh[2 * tj][1] = r4[2]; bh[2 * tj + 1][1] = r4[3];
                LDMATRIX_X4(r4, b_lo_b + off);
                bl[2 * tj][0] = r4[0]; bl[2 * tj + 1][0] = r4[1];
                bl[2 * tj][1] = r4[2]; bl[2 * tj + 1][1] = r4[3];
            }
            #pragma unroll
            for (int ti = 0; ti < 2; ti++)
                #pragma unroll
                for (int j = 0; j < 8; j++) {
                    mma16816(acc[ti][j], ah[ti], bh[j]);   // hi*hi
                    mma16816(acc[ti][j], ah[ti], bl[j]);   // hi*lo
                    mma16816(acc[ti][j], al[ti], bh[j]);   // lo*hi
                }
        }
    }

    // epilogue: d0,d1 -> (row, col..col+1); d2,d3 -> (row+8, ...)
    #pragma unroll
    for (int ti = 0; ti < 2; ti++) {
        const int r0 = m0 + wm + ti * 16 + (lane >> 2);
        #pragma unroll
        for (int j = 0; j < 8; j++) {
            const int c = n0 + wn + j * 8 + (lane & 3) * 2;
            if (r0 < NUM_NODES)
                *(float2*)&g_xl[(size_t)r0 * D_OUT + c] = make_float2(acc[ti][j][0], acc[ti][j][1]);
            if (r0 + 8 < NUM_NODES)
                *(float2*)&g_xl[(size_t)(r0 + 8) * D_OUT + c] = make_float2(acc[ti][j][2], acc[ti][j][3]);
        }
    }
}

// ---------------- exclusive scan (2 blocks; thread-sequential + shuffle scan) --
__global__ __launch_bounds__(1024) void scan_kernel() {
    const int* cnt = (blockIdx.x == 0) ? g_ecnt : g_ncnt;
    int* ptr       = (blockIdx.x == 0) ? g_eptr : g_nptr;
    const int n    = (blockIdx.x == 0) ? NUM_EDGES : NUM_NODES;
    const int IPT  = (n + 1023) / 1024;

    const int t    = threadIdx.x;
    const int lane = t & 31;
    const int wid  = t >> 5;
    int beg = t * IPT; if (beg > n) beg = n;
    int end = beg + IPT; if (end > n) end = n;

    int sum = 0;
    for (int i = beg; i < end; i++) sum += cnt[i];

    int v = sum;
    #pragma unroll
    for (int o = 1; o < 32; o <<= 1) {
        int u = __shfl_up_sync(0xffffffffu, v, o);
        if (lane >= o) v += u;
    }
    __shared__ int warp_sums[32];
    if (lane == 31) warp_sums[wid] = v;
    __syncthreads();
    if (wid == 0) {
        int wv = warp_sums[lane];
        #pragma unroll
        for (int o = 1; o < 32; o <<= 1) {
            int u = __shfl_up_sync(0xffffffffu, wv, o);
            if (lane >= o) wv += u;
        }
        warp_sums[lane] = wv;
    }
    __syncthreads();
    int excl = v - sum + ((wid > 0) ? warp_sums[wid - 1] : 0);

    int run = excl;
    for (int i = beg; i < end; i++) { ptr[i] = run; run += cnt[i]; }
    if (t == 1023) ptr[n] = run;
}

// ---------------- scatter nnz into both CSR structures ----------------
__global__ void scatter_kernel() {
    int t = blockIdx.x * blockDim.x + threadIdx.x;
    if (t >= NNZ) return;
    int n = g_nidx[t];
    int e = g_eidx[t];
    int p = g_eptr[e] + atomicAdd(&g_efill[e], 1);
    g_enodes[p] = n;
    int q = g_nptr[n] + atomicAdd(&g_nfill[n], 1);
    g_nedges[q] = e;
}

// ---------------- node -> hyperedge aggregation (float4, unroll x4) ----------
__global__ __launch_bounds__(256) void edge_agg_kernel() {
    const int grp  = threadIdx.x >> 6;
    const int lane = threadIdx.x & 63;
    const int e = blockIdx.x * 4 + grp;
    if (e >= NUM_EDGES) return;
    const int beg = __ldg(&g_eptr[e]);
    const int end = __ldg(&g_eptr[e + 1]);
    const float4* __restrict__ xl4 = (const float4*)g_xl;

    float ax = 0.f, ay = 0.f, az = 0.f, aw = 0.f;
    int j = beg;
    for (; j + 4 <= end; j += 4) {
        const int i0 = __ldg(&g_enodes[j]);
        const int i1 = __ldg(&g_enodes[j + 1]);
        const int i2 = __ldg(&g_enodes[j + 2]);
        const int i3 = __ldg(&g_enodes[j + 3]);
        float4 a = __ldg(&xl4[(size_t)i0 * 64 + lane]);
        float4 c = __ldg(&xl4[(size_t)i1 * 64 + lane]);
        float4 d = __ldg(&xl4[(size_t)i2 * 64 + lane]);
        float4 f = __ldg(&xl4[(size_t)i3 * 64 + lane]);
        ax += (a.x + c.x) + (d.x + f.x);
        ay += (a.y + c.y) + (d.y + f.y);
        az += (a.z + c.z) + (d.z + f.z);
        aw += (a.w + c.w) + (d.w + f.w);
    }
    for (; j < end; j++) {
        const int i0 = __ldg(&g_enodes[j]);
        float4 a = __ldg(&xl4[(size_t)i0 * 64 + lane]);
        ax += a.x; ay += a.y; az += a.z; aw += a.w;
    }
    const float card = (float)(end - beg);
    const float binv = (card > 0.f) ? (1.f / card) : 0.f;
    ((float4*)g_efeat)[(size_t)e * 64 + lane] =
        make_float4(ax * binv, ay * binv, az * binv, aw * binv);
}

// ---------------- hyperedge -> node aggregation + bias (unroll x4) -----------
__global__ __launch_bounds__(256) void node_agg_kernel(float* __restrict__ out,
                                                       const float* __restrict__ b) {
    const int grp  = threadIdx.x >> 6;
    const int lane = threadIdx.x & 63;
    const int n = blockIdx.x * 4 + grp;
    if (n >= NUM_NODES) return;
    const int beg = __ldg(&g_nptr[n]);
    const int end = __ldg(&g_nptr[n + 1]);
    const float4* __restrict__ ef4 = (const float4*)g_efeat;

    float ax = 0.f, ay = 0.f, az = 0.f, aw = 0.f;
    int j = beg;
    for (; j + 4 <= end; j += 4) {
        const int e0 = __ldg(&g_nedges[j]);
        const int e1 = __ldg(&g_nedges[j + 1]);
        const int e2 = __ldg(&g_nedges[j + 2]);
        const int e3 = __ldg(&g_nedges[j + 3]);
        float4 a = __ldg(&ef4[(size_t)e0 * 64 + lane]);
        float4 c = __ldg(&ef4[(size_t)e1 * 64 + lane]);
        float4 d = __ldg(&ef4[(size_t)e2 * 64 + lane]);
        float4 f = __ldg(&ef4[(size_t)e3 * 64 + lane]);
        ax += (a.x + c.x) + (d.x + f.x);
        ay += (a.y + c.y) + (d.y + f.y);
        az += (a.z + c.z) + (d.z + f.z);
        aw += (a.w + c.w) + (d.w + f.w);
    }
    for (; j < end; j++) {
        const int e0 = __ldg(&g_nedges[j]);
        float4 a = __ldg(&ef4[(size_t)e0 * 64 + lane]);
        ax += a.x; ay += a.y; az += a.z; aw += a.w;
    }
    const float d = __ldg(&g_D[n]);
    const float dinv = (d > 0.f) ? (1.f / d) : 0.f;
    const float4 bb = __ldg(&((const float4*)b)[lane]);
    ((float4*)out)[(size_t)n * 64 + lane] =
        make_float4(ax * dinv + bb.x, ay * dinv + bb.y,
                    az * dinv + bb.z, aw * dinv + bb.w);
}

// ---------------- launch ----------------
extern "C" void kernel_launch(void* const* d_in, const int* in_sizes, int n_in,
                              void* d_out, int out_size) {
    const float* x  = nullptr;
    const void*  hi = nullptr;
    const float* w  = nullptr;
    const float* W  = nullptr;
    const float* b  = nullptr;
    for (int i = 0; i < n_in; i++) {
        switch (in_sizes[i]) {
            case NUM_NODES * D_IN:   x  = (const float*)d_in[i]; break;
            case 2 * NNZ:            hi = d_in[i];               break;
            case NUM_EDGES:          w  = (const float*)d_in[i]; break;
            case D_IN * D_OUT:       W  = (const float*)d_in[i]; break;
            case D_OUT:              b  = (const float*)d_in[i]; break;
            default: break;
        }
    }
    float* out = (float*)d_out;

    probe_kernel<<<1, 256>>>((const unsigned int*)hi);
    zero_kernel<<<(NUM_NODES + 255) / 256, 256>>>();
    decode_count_kernel<<<(NNZ + 255) / 256, 256>>>(hi, w);

    split_w_kernel<<<(D_IN * D_OUT + 255) / 256, 256>>>(W);

    dim3 ggrid(D_OUT / 128, (NUM_NODES + 127) / 128);
    mma_gemm_kernel<<<ggrid, 256>>>(x);

    scan_kernel<<<2, 1024>>>();
    scatter_kernel<<<(NNZ + 255) / 256, 256>>>();

    edge_agg_kernel<<<(NUM_EDGES + 3) / 4, 256>>>();
    node_agg_kernel<<<(NUM_NODES + 3) / 4, 256>>>(out, b);
}

// round 10
// speedup vs baseline: 2.0716x; 1.0045x over previous
#include <cuda_runtime.h>
#include <cuda_bf16.h>
#include <cstdint>

#define NUM_NODES 50000
#define NUM_EDGES 50000
#define NNZ       500000
#define D_IN      256
#define D_OUT     256

// ---------------- static device scratch (no allocation allowed) ----------------
__device__ float g_xl[(size_t)NUM_NODES * D_OUT];      // x @ W
__device__ float g_efeat[(size_t)NUM_EDGES * D_OUT];   // per-hyperedge features
__device__ int   g_ecnt[NUM_EDGES];
__device__ int   g_ncnt[NUM_NODES];
__device__ int   g_eptr[NUM_EDGES + 1];
__device__ int   g_nptr[NUM_NODES + 1];
__device__ int   g_efill[NUM_EDGES];
__device__ int   g_nfill[NUM_NODES];
__device__ int   g_enodes[NNZ];
__device__ int   g_nedges[NNZ];
__device__ int   g_nidx[NNZ];
__device__ int   g_eidx[NNZ];
__device__ int   g_is64;
// split-bf16 W for HMMA GEMM (x is converted in-kernel)
__device__ __nv_bfloat16 g_whi[D_IN * D_OUT];          // stored [N][K] (K-major)
__device__ __nv_bfloat16 g_wlo[D_IN * D_OUT];

// ---------------- helpers ----------------
__device__ __forceinline__ uint32_t smem_to_u32(const void* p) {
    uint32_t a;
    asm("{ .reg .u64 t; cvta.to.shared.u64 t, %1; cvt.u32.u64 %0, t; }" : "=r"(a) : "l"(p));
    return a;
}
#define LDMATRIX_X4(r, addr) \
    asm volatile("ldmatrix.sync.aligned.m8n8.x4.shared.b16 {%0,%1,%2,%3}, [%4];" \
                 : "=r"((r)[0]), "=r"((r)[1]), "=r"((r)[2]), "=r"((r)[3]) : "r"(addr))
__device__ __forceinline__ void mma16816(float* d, const uint32_t* a, const uint32_t* b) {
    asm volatile("mma.sync.aligned.m16n8k16.row.col.f32.bf16.bf16.f32 "
                 "{%0,%1,%2,%3}, {%4,%5,%6,%7}, {%8,%9}, {%0,%1,%2,%3};"
                 : "+f"(d[0]), "+f"(d[1]), "+f"(d[2]), "+f"(d[3])
                 : "r"(a[0]), "r"(a[1]), "r"(a[2]), "r"(a[3]), "r"(b[0]), "r"(b[1]));
}
// 4 fp32 -> 2 packed bf16x2 (hi) + 2 packed bf16x2 (lo residual)
__device__ __forceinline__ void cvt4(const float4 v, uint32_t* hi2, uint32_t* lo2) {
    __nv_bfloat16 h0 = __float2bfloat16_rn(v.x), h1 = __float2bfloat16_rn(v.y);
    __nv_bfloat16 h2 = __float2bfloat16_rn(v.z), h3 = __float2bfloat16_rn(v.w);
    __nv_bfloat162 H0 = __halves2bfloat162(h0, h1);
    __nv_bfloat162 H1 = __halves2bfloat162(h2, h3);
    __nv_bfloat162 L0 = __halves2bfloat162(__float2bfloat16_rn(v.x - __bfloat162float(h0)),
                                           __float2bfloat16_rn(v.y - __bfloat162float(h1)));
    __nv_bfloat162 L1 = __halves2bfloat162(__float2bfloat16_rn(v.z - __bfloat162float(h2)),
                                           __float2bfloat16_rn(v.w - __bfloat162float(h3)));
    hi2[0] = *(uint32_t*)&H0; hi2[1] = *(uint32_t*)&H1;
    lo2[0] = *(uint32_t*)&L0; lo2[1] = *(uint32_t*)&L1;
}

// ---------------- probe index dtype (int64 vs int32) ----------------
__global__ void probe_kernel(const unsigned int* __restrict__ buf) {
    __shared__ int found_nonzero;
    if (threadIdx.x == 0) found_nonzero = 0;
    __syncthreads();
    for (int i = threadIdx.x; i < 512; i += blockDim.x)
        if (buf[2 * i + 1] != 0u) atomicExch(&found_nonzero, 1);
    __syncthreads();
    if (threadIdx.x == 0) g_is64 = found_nonzero ? 0 : 1;
}

// ---------------- zero counters ----------------
__global__ void zero_kernel() {
    int t = blockIdx.x * blockDim.x + threadIdx.x;
    if (t < NUM_NODES) { g_ncnt[t] = 0; g_nfill[t] = 0; }
    if (t < NUM_EDGES) { g_ecnt[t] = 0; g_efill[t] = 0; }
}

// ---------------- decode indices + histograms (fused) ----------------
__global__ void decode_count_kernel(const void* __restrict__ buf) {
    int t = blockIdx.x * blockDim.x + threadIdx.x;
    if (t >= NNZ) return;
    int n, e;
    if (g_is64) {
        const long long* p = (const long long*)buf;
        n = (int)p[t];
        e = (int)p[NNZ + t];
    } else {
        const int* p = (const int*)buf;
        n = p[t];
        e = p[NNZ + t];
    }
    if ((unsigned)n >= NUM_NODES) n = 0;
    if ((unsigned)e >= NUM_EDGES) e = 0;
    g_nidx[t] = n;
    g_eidx[t] = e;
    atomicAdd(&g_ecnt[e], 1);
    atomicAdd(&g_ncnt[n], 1);
}

// W[k][n] -> w_hi/w_lo stored [n][k] (K-major B for row.col mma)
__global__ void split_w_kernel(const float* __restrict__ W) {
    int t = blockIdx.x * blockDim.x + threadIdx.x;
    if (t >= D_IN * D_OUT) return;
    int n = t >> 8, k = t & 255;
    float v = __ldg(&W[k * D_OUT + n]);
    __nv_bfloat16 h = __float2bfloat16_rn(v);
    g_whi[n * D_IN + k] = h;
    g_wlo[n * D_IN + k] = __float2bfloat16_rn(v - __bfloat162float(h));
}

// ---------------- HMMA split-bf16 GEMM: g_xl = x @ W (fused fp32->hi/lo) ------
#define SPAD 40
__global__ __launch_bounds__(256, 2) void mma_gemm_kernel(const float* __restrict__ X) {
    __shared__ __nv_bfloat16 As_hi[128][SPAD], As_lo[128][SPAD];
    __shared__ __nv_bfloat16 Bs_hi[128][SPAD], Bs_lo[128][SPAD];

    const int tid  = threadIdx.x;
    const int lane = tid & 31;
    const int wid  = tid >> 5;
    const int wm   = (wid >> 1) * 32;
    const int wn   = (wid & 1) * 64;
    const int m0   = blockIdx.y * 128;
    const int n0   = blockIdx.x * 128;

    float acc[2][8][4];
    #pragma unroll
    for (int i = 0; i < 2; i++)
        #pragma unroll
        for (int j = 0; j < 8; j++)
            #pragma unroll
            for (int q = 0; q < 4; q++) acc[i][j][q] = 0.f;

    const uint32_t a_hi_b = smem_to_u32(&As_hi[0][0]);
    const uint32_t a_lo_b = smem_to_u32(&As_lo[0][0]);
    const uint32_t b_hi_b = smem_to_u32(&Bs_hi[0][0]);
    const uint32_t b_lo_b = smem_to_u32(&Bs_lo[0][0]);

    for (int kc = 0; kc < 8; kc++) {
        const int k0 = kc * 32;
        __syncthreads();
        #pragma unroll
        for (int i = tid; i < 512; i += 256) {
            const int r = i >> 2, seg = i & 3;
            const int gr = m0 + r;
            float4 v0 = make_float4(0.f, 0.f, 0.f, 0.f), v1 = v0;
            if (gr < NUM_NODES) {
                const float* src = X + (size_t)gr * D_IN + k0 + seg * 8;
                v0 = __ldg((const float4*)src);
                v1 = __ldg((const float4*)(src + 4));
            }
            uint32_t hi[4], lo[4];
            cvt4(v0, hi, lo);
            cvt4(v1, hi + 2, lo + 2);
            *(uint4*)&As_hi[r][seg * 8] = make_uint4(hi[0], hi[1], hi[2], hi[3]);
            *(uint4*)&As_lo[r][seg * 8] = make_uint4(lo[0], lo[1], lo[2], lo[3]);
            const int gn = n0 + r;
            *(uint4*)&Bs_hi[r][seg * 8] = *(const uint4*)(g_whi + (size_t)gn * D_IN + k0 + seg * 8);
            *(uint4*)&Bs_lo[r][seg * 8] = *(const uint4*)(g_wlo + (size_t)gn * D_IN + k0 + seg * 8);
        }
        __syncthreads();

        #pragma unroll
        for (int kk = 0; kk < 32; kk += 16) {
            uint32_t ah[2][4], al[2][4];
            #pragma unroll
            for (int ti = 0; ti < 2; ti++) {
                const int row = wm + ti * 16 + (lane & 15);
                const uint32_t off = (uint32_t)(row * (SPAD * 2) + (kk + (lane >> 4) * 8) * 2);
                LDMATRIX_X4(ah[ti], a_hi_b + off);
                LDMATRIX_X4(al[ti], a_lo_b + off);
            }
            uint32_t bh[8][2], bl[8][2];
            #pragma unroll
            for (int tj = 0; tj < 4; tj++) {
                const int row = wn + tj * 16 + (lane & 15);
                const uint32_t off = (uint32_t)(row * (SPAD * 2) + (kk + (lane >> 4) * 8) * 2);
                uint32_t r4[4];
                LDMATRIX_X4(r4, b_hi_b + off);
                bh[2 * tj][0] = r4[0]; bh[2 * tj + 1][0] = r4[1];
                bh[2 * tj][1] = r4[2]; bh[2 * tj + 1][1] = r4[3];
                LDMATRIX_X4(r4, b_lo_b + off);
                bl[2 * tj][0] = r4[0]; bl[2 * tj + 1][0] = r4[1];
                bl[2 * tj][1] = r4[2]; bl[2 * tj + 1][1] = r4[3];
            }
            #pragma unroll
            for (int ti = 0; ti < 2; ti++)
                #pragma unroll
                for (int j = 0; j < 8; j++) {
                    mma16816(acc[ti][j], ah[ti], bh[j]);
                    mma16816(acc[ti][j], ah[ti], bl[j]);
                    mma16816(acc[ti][j], al[ti], bh[j]);
                }
        }
    }

    #pragma unroll
    for (int ti = 0; ti < 2; ti++) {
        const int r0 = m0 + wm + ti * 16 + (lane >> 2);
        #pragma unroll
        for (int j = 0; j < 8; j++) {
            const int c = n0 + wn + j * 8 + (lane & 3) * 2;
            if (r0 < NUM_NODES)
                *(float2*)&g_xl[(size_t)r0 * D_OUT + c] = make_float2(acc[ti][j][0], acc[ti][j][1]);
            if (r0 + 8 < NUM_NODES)
                *(float2*)&g_xl[(size_t)(r0 + 8) * D_OUT + c] = make_float2(acc[ti][j][2], acc[ti][j][3]);
        }
    }
}

// ---------------- exclusive scan (2 blocks; thread-sequential + shuffle scan) --
__global__ __launch_bounds__(1024) void scan_kernel() {
    const int* cnt = (blockIdx.x == 0) ? g_ecnt : g_ncnt;
    int* ptr       = (blockIdx.x == 0) ? g_eptr : g_nptr;
    const int n    = (blockIdx.x == 0) ? NUM_EDGES : NUM_NODES;
    const int IPT  = (n + 1023) / 1024;

    const int t    = threadIdx.x;
    const int lane = t & 31;
    const int wid  = t >> 5;
    int beg = t * IPT; if (beg > n) beg = n;
    int end = beg + IPT; if (end > n) end = n;

    int sum = 0;
    for (int i = beg; i < end; i++) sum += cnt[i];

    int v = sum;
    #pragma unroll
    for (int o = 1; o < 32; o <<= 1) {
        int u = __shfl_up_sync(0xffffffffu, v, o);
        if (lane >= o) v += u;
    }
    __shared__ int warp_sums[32];
    if (lane == 31) warp_sums[wid] = v;
    __syncthreads();
    if (wid == 0) {
        int wv = warp_sums[lane];
        #pragma unroll
        for (int o = 1; o < 32; o <<= 1) {
            int u = __shfl_up_sync(0xffffffffu, wv, o);
            if (lane >= o) wv += u;
        }
        warp_sums[lane] = wv;
    }
    __syncthreads();
    int excl = v - sum + ((wid > 0) ? warp_sums[wid - 1] : 0);

    int run = excl;
    for (int i = beg; i < end; i++) { ptr[i] = run; run += cnt[i]; }
    if (t == 1023) ptr[n] = run;
}

// ---------------- scatter nnz into both CSR structures ----------------
__global__ void scatter_kernel() {
    int t = blockIdx.x * blockDim.x + threadIdx.x;
    if (t >= NNZ) return;
    int n = g_nidx[t];
    int e = g_eidx[t];
    int p = g_eptr[e] + atomicAdd(&g_efill[e], 1);
    g_enodes[p] = n;
    int q = g_nptr[n] + atomicAdd(&g_nfill[n], 1);
    g_nedges[q] = e;
}

// ---------------- node -> hyperedge aggregation (float4, unroll x4) ----------
__global__ __launch_bounds__(256) void edge_agg_kernel() {
    const int grp  = threadIdx.x >> 6;
    const int lane = threadIdx.x & 63;
    const int e = blockIdx.x * 4 + grp;
    if (e >= NUM_EDGES) return;
    const int beg = __ldg(&g_eptr[e]);
    const int end = __ldg(&g_eptr[e + 1]);
    const float4* __restrict__ xl4 = (const float4*)g_xl;

    float ax = 0.f, ay = 0.f, az = 0.f, aw = 0.f;
    int j = beg;
    for (; j + 4 <= end; j += 4) {
        const int i0 = __ldg(&g_enodes[j]);
        const int i1 = __ldg(&g_enodes[j + 1]);
        const int i2 = __ldg(&g_enodes[j + 2]);
        const int i3 = __ldg(&g_enodes[j + 3]);
        float4 a = __ldg(&xl4[(size_t)i0 * 64 + lane]);
        float4 c = __ldg(&xl4[(size_t)i1 * 64 + lane]);
        float4 d = __ldg(&xl4[(size_t)i2 * 64 + lane]);
        float4 f = __ldg(&xl4[(size_t)i3 * 64 + lane]);
        ax += (a.x + c.x) + (d.x + f.x);
        ay += (a.y + c.y) + (d.y + f.y);
        az += (a.z + c.z) + (d.z + f.z);
        aw += (a.w + c.w) + (d.w + f.w);
    }
    for (; j < end; j++) {
        const int i0 = __ldg(&g_enodes[j]);
        float4 a = __ldg(&xl4[(size_t)i0 * 64 + lane]);
        ax += a.x; ay += a.y; az += a.z; aw += a.w;
    }
    const float card = (float)(end - beg);
    const float binv = (card > 0.f) ? (1.f / card) : 0.f;
    ((float4*)g_efeat)[(size_t)e * 64 + lane] =
        make_float4(ax * binv, ay * binv, az * binv, aw * binv);
}

// -------- hyperedge -> node aggregation + bias; D computed from CSR ----------
__global__ __launch_bounds__(256) void node_agg_kernel(float* __restrict__ out,
                                                       const float* __restrict__ b,
                                                       const float* __restrict__ w) {
    const int grp  = threadIdx.x >> 6;
    const int lane = threadIdx.x & 63;
    const int n = blockIdx.x * 4 + grp;
    if (n >= NUM_NODES) return;
    const int beg = __ldg(&g_nptr[n]);
    const int end = __ldg(&g_nptr[n + 1]);
    const float4* __restrict__ ef4 = (const float4*)g_efeat;

    float ax = 0.f, ay = 0.f, az = 0.f, aw = 0.f;
    float dsum = 0.f;
    int j = beg;
    for (; j + 4 <= end; j += 4) {
        const int e0 = __ldg(&g_nedges[j]);
        const int e1 = __ldg(&g_nedges[j + 1]);
        const int e2 = __ldg(&g_nedges[j + 2]);
        const int e3 = __ldg(&g_nedges[j + 3]);
        float4 a = __ldg(&ef4[(size_t)e0 * 64 + lane]);
        float4 c = __ldg(&ef4[(size_t)e1 * 64 + lane]);
        float4 d = __ldg(&ef4[(size_t)e2 * 64 + lane]);
        float4 f = __ldg(&ef4[(size_t)e3 * 64 + lane]);
        dsum += (__ldg(&w[e0]) + __ldg(&w[e1])) + (__ldg(&w[e2]) + __ldg(&w[e3]));
        ax += (a.x + c.x) + (d.x + f.x);
        ay += (a.y + c.y) + (d.y + f.y);
        az += (a.z + c.z) + (d.z + f.z);
        aw += (a.w + c.w) + (d.w + f.w);
    }
    for (; j < end; j++) {
        const int e0 = __ldg(&g_nedges[j]);
        float4 a = __ldg(&ef4[(size_t)e0 * 64 + lane]);
        dsum += __ldg(&w[e0]);
        ax += a.x; ay += a.y; az += a.z; aw += a.w;
    }
    const float dinv = (dsum > 0.f) ? (1.f / dsum) : 0.f;
    const float4 bb = __ldg(&((const float4*)b)[lane]);
    ((float4*)out)[(size_t)n * 64 + lane] =
        make_float4(ax * dinv + bb.x, ay * dinv + bb.y,
                    az * dinv + bb.z, aw * dinv + bb.w);
}

// ---------------- launch ----------------
extern "C" void kernel_launch(void* const* d_in, const int* in_sizes, int n_in,
                              void* d_out, int out_size) {
    const float* x  = nullptr;
    const void*  hi = nullptr;
    const float* w  = nullptr;
    const float* W  = nullptr;
    const float* b  = nullptr;
    for (int i = 0; i < n_in; i++) {
        switch (in_sizes[i]) {
            case NUM_NODES * D_IN:   x  = (const float*)d_in[i]; break;
            case 2 * NNZ:            hi = d_in[i];               break;
            case NUM_EDGES:          w  = (const float*)d_in[i]; break;
            case D_IN * D_OUT:       W  = (const float*)d_in[i]; break;
            case D_OUT:              b  = (const float*)d_in[i]; break;
            default: break;
        }
    }
    float* out = (float*)d_out;

    // side stream for the GEMM chain (created per call; kernel_launch is only
    // invoked for correctness + capture, so this is bounded and deterministic)
    cudaStream_t s1;
    cudaStreamCreate(&s1);
    cudaEvent_t evFork, evJoin;
    cudaEventCreateWithFlags(&evFork, cudaEventDisableTiming);
    cudaEventCreateWithFlags(&evJoin, cudaEventDisableTiming);

    // fork: GEMM chain depends on nothing upstream
    cudaEventRecord(evFork, 0);
    cudaStreamWaitEvent(s1, evFork, 0);
    split_w_kernel<<<(D_IN * D_OUT + 255) / 256, 256, 0, s1>>>(W);
    dim3 ggrid(D_OUT / 128, (NUM_NODES + 127) / 128);
    mma_gemm_kernel<<<ggrid, 256, 0, s1>>>(x);
    cudaEventRecord(evJoin, s1);

    // main stream: CSR build chain
    probe_kernel<<<1, 256>>>((const unsigned int*)hi);
    zero_kernel<<<(NUM_NODES + 255) / 256, 256>>>();
    decode_count_kernel<<<(NNZ + 255) / 256, 256>>>(hi);
    scan_kernel<<<2, 1024>>>();
    scatter_kernel<<<(NNZ + 255) / 256, 256>>>();

    // join: aggregations need both chains
    cudaStreamWaitEvent(0, evJoin, 0);
    edge_agg_kernel<<<(NUM_EDGES + 3) / 4, 256>>>();
    node_agg_kernel<<<(NUM_NODES + 3) / 4, 256>>>(out, b, w);
}

// round 12
// speedup vs baseline: 2.3748x; 1.1464x over previous
#include <cuda_runtime.h>
#include <cuda_fp16.h>
#include <cstdint>

#define NUM_NODES 50000
#define NUM_EDGES 50000
#define NNZ       500000
#define D_IN      256
#define D_OUT     256

// ---------------- static device scratch (no allocation allowed) ----------------
__device__ float g_xl[(size_t)NUM_NODES * D_OUT];      // x @ W
__device__ float g_efeat[(size_t)NUM_EDGES * D_OUT];   // per-hyperedge features
__device__ int   g_ecnt[NUM_EDGES];
__device__ int   g_ncnt[NUM_NODES];
__device__ int   g_eptr[NUM_EDGES + 1];
__device__ int   g_nptr[NUM_NODES + 1];
__device__ int   g_efill[NUM_EDGES];
__device__ int   g_nfill[NUM_NODES];
__device__ int   g_enodes[NNZ];
__device__ int   g_nedges[NNZ];
__device__ int   g_nidx[NNZ];
__device__ int   g_eidx[NNZ];
__device__ int   g_is64;
// fp16 W for HMMA GEMM (x is split to fp16 hi/lo in-kernel)
__device__ __half g_wh[D_IN * D_OUT];                  // stored [N][K] (K-major)

// ---------------- helpers ----------------
__device__ __forceinline__ uint32_t smem_to_u32(const void* p) {
    uint32_t a;
    asm("{ .reg .u64 t; cvta.to.shared.u64 t, %1; cvt.u32.u64 %0, t; }" : "=r"(a) : "l"(p));
    return a;
}
#define LDMATRIX_X4(r, addr) \
    asm volatile("ldmatrix.sync.aligned.m8n8.x4.shared.b16 {%0,%1,%2,%3}, [%4];" \
                 : "=r"((r)[0]), "=r"((r)[1]), "=r"((r)[2]), "=r"((r)[3]) : "r"(addr))
__device__ __forceinline__ void mma16816(float* d, const uint32_t* a, const uint32_t* b) {
    asm volatile("mma.sync.aligned.m16n8k16.row.col.f32.f16.f16.f32 "
                 "{%0,%1,%2,%3}, {%4,%5,%6,%7}, {%8,%9}, {%0,%1,%2,%3};"
                 : "+f"(d[0]), "+f"(d[1]), "+f"(d[2]), "+f"(d[3])
                 : "r"(a[0]), "r"(a[1]), "r"(a[2]), "r"(a[3]), "r"(b[0]), "r"(b[1]));
}
// 4 fp32 -> 2 packed f16x2 (hi) + 2 packed f16x2 (lo residual)
__device__ __forceinline__ void cvt4(const float4 v, uint32_t* hi2, uint32_t* lo2) {
    __half h0 = __float2half_rn(v.x), h1 = __float2half_rn(v.y);
    __half h2 = __float2half_rn(v.z), h3 = __float2half_rn(v.w);
    __half2 H0 = __halves2half2(h0, h1);
    __half2 H1 = __halves2half2(h2, h3);
    __half2 L0 = __halves2half2(__float2half_rn(v.x - __half2float(h0)),
                                __float2half_rn(v.y - __half2float(h1)));
    __half2 L1 = __halves2half2(__float2half_rn(v.z - __half2float(h2)),
                                __float2half_rn(v.w - __half2float(h3)));
    hi2[0] = *(uint32_t*)&H0; hi2[1] = *(uint32_t*)&H1;
    lo2[0] = *(uint32_t*)&L0; lo2[1] = *(uint32_t*)&L1;
}

// ---------------- probe index dtype (int64 vs int32) ----------------
__global__ void probe_kernel(const unsigned int* __restrict__ buf) {
    __shared__ int found_nonzero;
    if (threadIdx.x == 0) found_nonzero = 0;
    __syncthreads();
    for (int i = threadIdx.x; i < 512; i += blockDim.x)
        if (buf[2 * i + 1] != 0u) atomicExch(&found_nonzero, 1);
    __syncthreads();
    if (threadIdx.x == 0) g_is64 = found_nonzero ? 0 : 1;
}

// ---------------- zero counters ----------------
__global__ void zero_kernel() {
    int t = blockIdx.x * blockDim.x + threadIdx.x;
    if (t < NUM_NODES) { g_ncnt[t] = 0; g_nfill[t] = 0; }
    if (t < NUM_EDGES) { g_ecnt[t] = 0; g_efill[t] = 0; }
}

// ---------------- decode indices + histograms (fused) ----------------
__global__ void decode_count_kernel(const void* __restrict__ buf) {
    int t = blockIdx.x * blockDim.x + threadIdx.x;
    if (t >= NNZ) return;
    int n, e;
    if (g_is64) {
        const long long* p = (const long long*)buf;
        n = (int)p[t];
        e = (int)p[NNZ + t];
    } else {
        const int* p = (const int*)buf;
        n = p[t];
        e = p[NNZ + t];
    }
    if ((unsigned)n >= NUM_NODES) n = 0;
    if ((unsigned)e >= NUM_EDGES) e = 0;
    g_nidx[t] = n;
    g_eidx[t] = e;
    atomicAdd(&g_ecnt[e], 1);
    atomicAdd(&g_ncnt[n], 1);
}

// W[k][n] -> fp16, stored [n][k] (K-major B for row.col mma)
__global__ void conv_w_kernel(const float* __restrict__ W) {
    int t = blockIdx.x * blockDim.x + threadIdx.x;
    if (t >= D_IN * D_OUT) return;
    int n = t >> 8, k = t & 255;
    g_wh[n * D_IN + k] = __float2half_rn(__ldg(&W[k * D_OUT + n]));
}

// ---------------- HMMA fp16-split GEMM: g_xl = x @ W (2 passes) --------------
// CTA 128x128, 8 warps (4x2), warp tile 32x64, K chunks of 32.
// smem rows padded to 40 halves (80B) -> conflict-free ldmatrix.
#define SPAD 40
__global__ __launch_bounds__(256, 2) void mma_gemm_kernel(const float* __restrict__ X) {
    __shared__ __half As_hi[128][SPAD], As_lo[128][SPAD];
    __shared__ __half Bs[128][SPAD];

    const int tid  = threadIdx.x;
    const int lane = tid & 31;
    const int wid  = tid >> 5;
    const int wm   = (wid >> 1) * 32;
    const int wn   = (wid & 1) * 64;
    const int m0   = blockIdx.y * 128;
    const int n0   = blockIdx.x * 128;

    float acc[2][8][4];
    #pragma unroll
    for (int i = 0; i < 2; i++)
        #pragma unroll
        for (int j = 0; j < 8; j++)
            #pragma unroll
            for (int q = 0; q < 4; q++) acc[i][j][q] = 0.f;

    const uint32_t a_hi_b = smem_to_u32(&As_hi[0][0]);
    const uint32_t a_lo_b = smem_to_u32(&As_lo[0][0]);
    const uint32_t b_b    = smem_to_u32(&Bs[0][0]);

    for (int kc = 0; kc < 8; kc++) {
        const int k0 = kc * 32;
        __syncthreads();
        #pragma unroll
        for (int i = tid; i < 512; i += 256) {
            const int r = i >> 2, seg = i & 3;     // seg: 8 elements
            const int gr = m0 + r;
            float4 v0 = make_float4(0.f, 0.f, 0.f, 0.f), v1 = v0;
            if (gr < NUM_NODES) {
                const float* src = X + (size_t)gr * D_IN + k0 + seg * 8;
                v0 = __ldg((const float4*)src);
                v1 = __ldg((const float4*)(src + 4));
            }
            uint32_t hi[4], lo[4];
            cvt4(v0, hi, lo);
            cvt4(v1, hi + 2, lo + 2);
            *(uint4*)&As_hi[r][seg * 8] = make_uint4(hi[0], hi[1], hi[2], hi[3]);
            *(uint4*)&As_lo[r][seg * 8] = make_uint4(lo[0], lo[1], lo[2], lo[3]);
            const int gn = n0 + r;
            *(uint4*)&Bs[r][seg * 8] = *(const uint4*)(g_wh + (size_t)gn * D_IN + k0 + seg * 8);
        }
        __syncthreads();

        #pragma unroll
        for (int kk = 0; kk < 32; kk += 16) {
            uint32_t ah[2][4], al[2][4];
            #pragma unroll
            for (int ti = 0; ti < 2; ti++) {
                const int row = wm + ti * 16 + (lane & 15);
                const uint32_t off = (uint32_t)(row * (SPAD * 2) + (kk + (lane >> 4) * 8) * 2);
                LDMATRIX_X4(ah[ti], a_hi_b + off);
                LDMATRIX_X4(al[ti], a_lo_b + off);
            }
            uint32_t bh[8][2];
            #pragma unroll
            for (int tj = 0; tj < 4; tj++) {
                const int row = wn + tj * 16 + (lane & 15);
                const uint32_t off = (uint32_t)(row * (SPAD * 2) + (kk + (lane >> 4) * 8) * 2);
                uint32_t r4[4];
                LDMATRIX_X4(r4, b_b + off);
                bh[2 * tj][0] = r4[0]; bh[2 * tj + 1][0] = r4[1];
                bh[2 * tj][1] = r4[2]; bh[2 * tj + 1][1] = r4[3];
            }
            #pragma unroll
            for (int ti = 0; ti < 2; ti++)
                #pragma unroll
                for (int j = 0; j < 8; j++) {
                    mma16816(acc[ti][j], ah[ti], bh[j]);   // hi * W
                    mma16816(acc[ti][j], al[ti], bh[j]);   // lo * W
                }
        }
    }

    #pragma unroll
    for (int ti = 0; ti < 2; ti++) {
        const int r0 = m0 + wm + ti * 16 + (lane >> 2);
        #pragma unroll
        for (int j = 0; j < 8; j++) {
            const int c = n0 + wn + j * 8 + (lane & 3) * 2;
            if (r0 < NUM_NODES)
                *(float2*)&g_xl[(size_t)r0 * D_OUT + c] = make_float2(acc[ti][j][0], acc[ti][j][1]);
            if (r0 + 8 < NUM_NODES)
                *(float2*)&g_xl[(size_t)(r0 + 8) * D_OUT + c] = make_float2(acc[ti][j][2], acc[ti][j][3]);
        }
    }
}

// ---------------- exclusive scan (2 blocks; thread-sequential + shuffle scan) --
__global__ __launch_bounds__(1024) void scan_kernel() {
    const int* cnt = (blockIdx.x == 0) ? g_ecnt : g_ncnt;
    int* ptr       = (blockIdx.x == 0) ? g_eptr : g_nptr;
    const int n    = (blockIdx.x == 0) ? NUM_EDGES : NUM_NODES;
    const int IPT  = (n + 1023) / 1024;

    const int t    = threadIdx.x;
    const int lane = t & 31;
    const int wid  = t >> 5;
    int beg = t * IPT; if (beg > n) beg = n;
    int end = beg + IPT; if (end > n) end = n;

    int sum = 0;
    for (int i = beg; i < end; i++) sum += cnt[i];

    int v = sum;
    #pragma unroll
    for (int o = 1; o < 32; o <<= 1) {
        int u = __shfl_up_sync(0xffffffffu, v, o);
        if (lane >= o) v += u;
    }
    __shared__ int warp_sums[32];
    if (lane == 31) warp_sums[wid] = v;
    __syncthreads();
    if (wid == 0) {
        int wv = warp_sums[lane];
        #pragma unroll
        for (int o = 1; o < 32; o <<= 1) {
            int u = __shfl_up_sync(0xffffffffu, wv, o);
            if (lane >= o) wv += u;
        }
        warp_sums[lane] = wv;
    }
    __syncthreads();
    int excl = v - sum + ((wid > 0) ? warp_sums[wid - 1] : 0);

    int run = excl;
    for (int i = beg; i < end; i++) { ptr[i] = run; run += cnt[i]; }
    if (t == 1023) ptr[n] = run;
}

// ---------------- scatter nnz into both CSR structures ----------------
__global__ void scatter_kernel() {
    int t = blockIdx.x * blockDim.x + threadIdx.x;
    if (t >= NNZ) return;
    int n = g_nidx[t];
    int e = g_eidx[t];
    int p = g_eptr[e] + atomicAdd(&g_efill[e], 1);
    g_enodes[p] = n;
    int q = g_nptr[n] + atomicAdd(&g_nfill[n], 1);
    g_nedges[q] = e;
}

// ---------------- node -> hyperedge aggregation (float4, unroll x4) ----------
__global__ __launch_bounds__(256) void edge_agg_kernel() {
    const int grp  = threadIdx.x >> 6;
    const int lane = threadIdx.x & 63;
    const int e = blockIdx.x * 4 + grp;
    if (e >= NUM_EDGES) return;
    const int beg = __ldg(&g_eptr[e]);
    const int end = __ldg(&g_eptr[e + 1]);
    const float4* __restrict__ xl4 = (const float4*)g_xl;

    float ax = 0.f, ay = 0.f, az = 0.f, aw = 0.f;
    int j = beg;
    for (; j + 4 <= end; j += 4) {
        const int i0 = __ldg(&g_enodes[j]);
        const int i1 = __ldg(&g_enodes[j + 1]);
        const int i2 = __ldg(&g_enodes[j + 2]);
        const int i3 = __ldg(&g_enodes[j + 3]);
        float4 a = __ldg(&xl4[(size_t)i0 * 64 + lane]);
        float4 c = __ldg(&xl4[(size_t)i1 * 64 + lane]);
        float4 d = __ldg(&xl4[(size_t)i2 * 64 + lane]);
        float4 f = __ldg(&xl4[(size_t)i3 * 64 + lane]);
        ax += (a.x + c.x) + (d.x + f.x);
        ay += (a.y + c.y) + (d.y + f.y);
        az += (a.z + c.z) + (d.z + f.z);
        aw += (a.w + c.w) + (d.w + f.w);
    }
    for (; j < end; j++) {
        const int i0 = __ldg(&g_enodes[j]);
        float4 a = __ldg(&xl4[(size_t)i0 * 64 + lane]);
        ax += a.x; ay += a.y; az += a.z; aw += a.w;
    }
    const float card = (float)(end - beg);
    const float binv = (card > 0.f) ? (1.f / card) : 0.f;
    ((float4*)g_efeat)[(size_t)e * 64 + lane] =
        make_float4(ax * binv, ay * binv, az * binv, aw * binv);
}

// -------- hyperedge -> node aggregation + bias; D computed from CSR ----------
__global__ __launch_bounds__(256) void node_agg_kernel(float* __restrict__ out,
                                                       const float* __restrict__ b,
                                                       const float* __restrict__ w) {
    const int grp  = threadIdx.x >> 6;
    const int lane = threadIdx.x & 63;
    const int n = blockIdx.x * 4 + grp;
    if (n >= NUM_NODES) return;
    const int beg = __ldg(&g_nptr[n]);
    const int end = __ldg(&g_nptr[n + 1]);
    const float4* __restrict__ ef4 = (const float4*)g_efeat;

    float ax = 0.f, ay = 0.f, az = 0.f, aw = 0.f;
    float dsum = 0.f;
    int j = beg;
    for (; j + 4 <= end; j += 4) {
        const int e0 = __ldg(&g_nedges[j]);
        const int e1 = __ldg(&g_nedges[j + 1]);
        const int e2 = __ldg(&g_nedges[j + 2]);
        const int e3 = __ldg(&g_nedges[j + 3]);
        float4 a = __ldg(&ef4[(size_t)e0 * 64 + lane]);
        float4 c = __ldg(&ef4[(size_t)e1 * 64 + lane]);
        float4 d = __ldg(&ef4[(size_t)e2 * 64 + lane]);
        float4 f = __ldg(&ef4[(size_t)e3 * 64 + lane]);
        dsum += (__ldg(&w[e0]) + __ldg(&w[e1])) + (__ldg(&w[e2]) + __ldg(&w[e3]));
        ax += (a.x + c.x) + (d.x + f.x);
        ay += (a.y + c.y) + (d.y + f.y);
        az += (a.z + c.z) + (d.z + f.z);
        aw += (a.w + c.w) + (d.w + f.w);
    }
    for (; j < end; j++) {
        const int e0 = __ldg(&g_nedges[j]);
        float4 a = __ldg(&ef4[(size_t)e0 * 64 + lane]);
        dsum += __ldg(&w[e0]);
        ax += a.x; ay += a.y; az += a.z; aw += a.w;
    }
    const float dinv = (dsum > 0.f) ? (1.f / dsum) : 0.f;
    const float4 bb = __ldg(&((const float4*)b)[lane]);
    ((float4*)out)[(size_t)n * 64 + lane] =
        make_float4(ax * dinv + bb.x, ay * dinv + bb.y,
                    az * dinv + bb.z, aw * dinv + bb.w);
}

// ---------------- launch ----------------
extern "C" void kernel_launch(void* const* d_in, const int* in_sizes, int n_in,
                              void* d_out, int out_size) {
    const float* x  = nullptr;
    const void*  hi = nullptr;
    const float* w  = nullptr;
    const float* W  = nullptr;
    const float* b  = nullptr;
    for (int i = 0; i < n_in; i++) {
        switch (in_sizes[i]) {
            case NUM_NODES * D_IN:   x  = (const float*)d_in[i]; break;
            case 2 * NNZ:            hi = d_in[i];               break;
            case NUM_EDGES:          w  = (const float*)d_in[i]; break;
            case D_IN * D_OUT:       W  = (const float*)d_in[i]; break;
            case D_OUT:              b  = (const float*)d_in[i]; break;
            default: break;
        }
    }
    float* out = (float*)d_out;

    cudaStream_t s1;
    cudaStreamCreate(&s1);
    cudaEvent_t evFork, evJoin;
    cudaEventCreateWithFlags(&evFork, cudaEventDisableTiming);
    cudaEventCreateWithFlags(&evJoin, cudaEventDisableTiming);

    // fork: GEMM chain
    cudaEventRecord(evFork, 0);
    cudaStreamWaitEvent(s1, evFork, 0);
    conv_w_kernel<<<(D_IN * D_OUT + 255) / 256, 256, 0, s1>>>(W);
    dim3 ggrid(D_OUT / 128, (NUM_NODES + 127) / 128);
    mma_gemm_kernel<<<ggrid, 256, 0, s1>>>(x);
    cudaEventRecord(evJoin, s1);

    // main stream: CSR build chain
    probe_kernel<<<1, 256>>>((const unsigned int*)hi);
    zero_kernel<<<(NUM_NODES + 255) / 256, 256>>>();
    decode_count_kernel<<<(NNZ + 255) / 256, 256>>>(hi);
    scan_kernel<<<2, 1024>>>();
    scatter_kernel<<<(NNZ + 255) / 256, 256>>>();

    // join: aggregations need both chains
    cudaStreamWaitEvent(0, evJoin, 0);
    edge_agg_kernel<<<(NUM_EDGES + 3) / 4, 256>>>();
    node_agg_kernel<<<(NUM_NODES + 3) / 4, 256>>>(out, b, w);
}

// round 14
// speedup vs baseline: 2.5489x; 1.0733x over previous
#include <cuda_runtime.h>
#include <cuda_fp16.h>
#include <cstdint>

#define NUM_NODES 50000
#define NUM_EDGES 50000
#define NNZ       500000
#define D_IN      256
#define D_OUT     256

// ---------------- static device scratch (no allocation allowed) ----------------
__device__ __half g_xlh[(size_t)NUM_NODES * D_OUT];    // x @ W (fp16 storage)
__device__ __half g_efh[(size_t)NUM_EDGES * D_OUT];    // per-hyperedge feats (fp16)
__device__ int   g_ecnt[NUM_EDGES];
__device__ int   g_ncnt[NUM_NODES];
__device__ int   g_eptr[NUM_EDGES + 1];
__device__ int   g_nptr[NUM_NODES + 1];
__device__ int   g_efill[NUM_EDGES];
__device__ int   g_nfill[NUM_NODES];
__device__ int   g_enodes[NNZ];
__device__ int   g_nedges[NNZ];
__device__ int   g_nidx[NNZ];
__device__ int   g_eidx[NNZ];
__device__ int   g_is64;
// fp16 W for HMMA GEMM (x is split to fp16 hi/lo in-kernel)
__device__ __half g_wh[D_IN * D_OUT];                  // stored [N][K] (K-major)

// ---------------- helpers ----------------
__device__ __forceinline__ uint32_t smem_to_u32(const void* p) {
    uint32_t a;
    asm("{ .reg .u64 t; cvta.to.shared.u64 t, %1; cvt.u32.u64 %0, t; }" : "=r"(a) : "l"(p));
    return a;
}
#define LDMATRIX_X4(r, addr) \
    asm volatile("ldmatrix.sync.aligned.m8n8.x4.shared.b16 {%0,%1,%2,%3}, [%4];" \
                 : "=r"((r)[0]), "=r"((r)[1]), "=r"((r)[2]), "=r"((r)[3]) : "r"(addr))
__device__ __forceinline__ void mma16816(float* d, const uint32_t* a, const uint32_t* b) {
    asm volatile("mma.sync.aligned.m16n8k16.row.col.f32.f16.f16.f32 "
                 "{%0,%1,%2,%3}, {%4,%5,%6,%7}, {%8,%9}, {%0,%1,%2,%3};"
                 : "+f"(d[0]), "+f"(d[1]), "+f"(d[2]), "+f"(d[3])
                 : "r"(a[0]), "r"(a[1]), "r"(a[2]), "r"(a[3]), "r"(b[0]), "r"(b[1]));
}
// 4 fp32 -> 2 packed f16x2 (hi) + 2 packed f16x2 (lo residual)
__device__ __forceinline__ void cvt4(const float4 v, uint32_t* hi2, uint32_t* lo2) {
    __half h0 = __float2half_rn(v.x), h1 = __float2half_rn(v.y);
    __half h2 = __float2half_rn(v.z), h3 = __float2half_rn(v.w);
    __half2 H0 = __halves2half2(h0, h1);
    __half2 H1 = __halves2half2(h2, h3);
    __half2 L0 = __halves2half2(__float2half_rn(v.x - __half2float(h0)),
                                __float2half_rn(v.y - __half2float(h1)));
    __half2 L1 = __halves2half2(__float2half_rn(v.z - __half2float(h2)),
                                __float2half_rn(v.w - __half2float(h3)));
    hi2[0] = *(uint32_t*)&H0; hi2[1] = *(uint32_t*)&H1;
    lo2[0] = *(uint32_t*)&L0; lo2[1] = *(uint32_t*)&L1;
}

// ---------------- probe index dtype (int64 vs int32) ----------------
__global__ void probe_kernel(const unsigned int* __restrict__ buf) {
    __shared__ int found_nonzero;
    if (threadIdx.x == 0) found_nonzero = 0;
    __syncthreads();
    for (int i = threadIdx.x; i < 512; i += blockDim.x)
        if (buf[2 * i + 1] != 0u) atomicExch(&found_nonzero, 1);
    __syncthreads();
    if (threadIdx.x == 0) g_is64 = found_nonzero ? 0 : 1;
}

// ---------------- zero counters ----------------
__global__ void zero_kernel() {
    int t = blockIdx.x * blockDim.x + threadIdx.x;
    if (t < NUM_NODES) { g_ncnt[t] = 0; g_nfill[t] = 0; }
    if (t < NUM_EDGES) { g_ecnt[t] = 0; g_efill[t] = 0; }
}

// ---------------- decode indices + histograms (fused) ----------------
__global__ void decode_count_kernel(const void* __restrict__ buf) {
    int t = blockIdx.x * blockDim.x + threadIdx.x;
    if (t >= NNZ) return;
    int n, e;
    if (g_is64) {
        const long long* p = (const long long*)buf;
        n = (int)p[t];
        e = (int)p[NNZ + t];
    } else {
        const int* p = (const int*)buf;
        n = p[t];
        e = p[NNZ + t];
    }
    if ((unsigned)n >= NUM_NODES) n = 0;
    if ((unsigned)e >= NUM_EDGES) e = 0;
    g_nidx[t] = n;
    g_eidx[t] = e;
    atomicAdd(&g_ecnt[e], 1);
    atomicAdd(&g_ncnt[n], 1);
}

// W[k][n] -> fp16, stored [n][k] (K-major B for row.col mma)
__global__ void conv_w_kernel(const float* __restrict__ W) {
    int t = blockIdx.x * blockDim.x + threadIdx.x;
    if (t >= D_IN * D_OUT) return;
    int n = t >> 8, k = t & 255;
    g_wh[n * D_IN + k] = __float2half_rn(__ldg(&W[k * D_OUT + n]));
}

// ---------------- HMMA fp16-split GEMM: g_xlh = x @ W (2 passes) -------------
#define SPAD 40
__global__ __launch_bounds__(256, 2) void mma_gemm_kernel(const float* __restrict__ X) {
    __shared__ __half As_hi[128][SPAD], As_lo[128][SPAD];
    __shared__ __half Bs[128][SPAD];

    const int tid  = threadIdx.x;
    const int lane = tid & 31;
    const int wid  = tid >> 5;
    const int wm   = (wid >> 1) * 32;
    const int wn   = (wid & 1) * 64;
    const int m0   = blockIdx.y * 128;
    const int n0   = blockIdx.x * 128;

    float acc[2][8][4];
    #pragma unroll
    for (int i = 0; i < 2; i++)
        #pragma unroll
        for (int j = 0; j < 8; j++)
            #pragma unroll
            for (int q = 0; q < 4; q++) acc[i][j][q] = 0.f;

    const uint32_t a_hi_b = smem_to_u32(&As_hi[0][0]);
    const uint32_t a_lo_b = smem_to_u32(&As_lo[0][0]);
    const uint32_t b_b    = smem_to_u32(&Bs[0][0]);

    for (int kc = 0; kc < 8; kc++) {
        const int k0 = kc * 32;
        __syncthreads();
        #pragma unroll
        for (int i = tid; i < 512; i += 256) {
            const int r = i >> 2, seg = i & 3;
            const int gr = m0 + r;
            float4 v0 = make_float4(0.f, 0.f, 0.f, 0.f), v1 = v0;
            if (gr < NUM_NODES) {
                const float* src = X + (size_t)gr * D_IN + k0 + seg * 8;
                v0 = __ldg((const float4*)src);
                v1 = __ldg((const float4*)(src + 4));
            }
            uint32_t hi[4], lo[4];
            cvt4(v0, hi, lo);
            cvt4(v1, hi + 2, lo + 2);
            *(uint4*)&As_hi[r][seg * 8] = make_uint4(hi[0], hi[1], hi[2], hi[3]);
            *(uint4*)&As_lo[r][seg * 8] = make_uint4(lo[0], lo[1], lo[2], lo[3]);
            const int gn = n0 + r;
            *(uint4*)&Bs[r][seg * 8] = *(const uint4*)(g_wh + (size_t)gn * D_IN + k0 + seg * 8);
        }
        __syncthreads();

        #pragma unroll
        for (int kk = 0; kk < 32; kk += 16) {
            uint32_t ah[2][4], al[2][4];
            #pragma unroll
            for (int ti = 0; ti < 2; ti++) {
                const int row = wm + ti * 16 + (lane & 15);
                const uint32_t off = (uint32_t)(row * (SPAD * 2) + (kk + (lane >> 4) * 8) * 2);
                LDMATRIX_X4(ah[ti], a_hi_b + off);
                LDMATRIX_X4(al[ti], a_lo_b + off);
            }
            uint32_t bh[8][2];
            #pragma unroll
            for (int tj = 0; tj < 4; tj++) {
                const int row = wn + tj * 16 + (lane & 15);
                const uint32_t off = (uint32_t)(row * (SPAD * 2) + (kk + (lane >> 4) * 8) * 2);
                uint32_t r4[4];
                LDMATRIX_X4(r4, b_b + off);
                bh[2 * tj][0] = r4[0]; bh[2 * tj + 1][0] = r4[1];
                bh[2 * tj][1] = r4[2]; bh[2 * tj + 1][1] = r4[3];
            }
            #pragma unroll
            for (int ti = 0; ti < 2; ti++)
                #pragma unroll
                for (int j = 0; j < 8; j++) {
                    mma16816(acc[ti][j], ah[ti], bh[j]);   // hi * W
                    mma16816(acc[ti][j], al[ti], bh[j]);   // lo * W
                }
        }
    }

    // epilogue: write fp16 pairs
    #pragma unroll
    for (int ti = 0; ti < 2; ti++) {
        const int r0 = m0 + wm + ti * 16 + (lane >> 2);
        #pragma unroll
        for (int j = 0; j < 8; j++) {
            const int c = n0 + wn + j * 8 + (lane & 3) * 2;
            if (r0 < NUM_NODES)
                *(__half2*)&g_xlh[(size_t)r0 * D_OUT + c] =
                    __floats2half2_rn(acc[ti][j][0], acc[ti][j][1]);
            if (r0 + 8 < NUM_NODES)
                *(__half2*)&g_xlh[(size_t)(r0 + 8) * D_OUT + c] =
                    __floats2half2_rn(acc[ti][j][2], acc[ti][j][3]);
        }
    }
}

// ---------------- exclusive scan (2 blocks; thread-sequential + shuffle scan) --
__global__ __launch_bounds__(1024) void scan_kernel() {
    const int* cnt = (blockIdx.x == 0) ? g_ecnt : g_ncnt;
    int* ptr       = (blockIdx.x == 0) ? g_eptr : g_nptr;
    const int n    = (blockIdx.x == 0) ? NUM_EDGES : NUM_NODES;
    const int IPT  = (n + 1023) / 1024;

    const int t    = threadIdx.x;
    const int lane = t & 31;
    const int wid  = t >> 5;
    int beg = t * IPT; if (beg > n) beg = n;
    int end = beg + IPT; if (end > n) end = n;

    int sum = 0;
    for (int i = beg; i < end; i++) sum += cnt[i];

    int v = sum;
    #pragma unroll
    for (int o = 1; o < 32; o <<= 1) {
        int u = __shfl_up_sync(0xffffffffu, v, o);
        if (lane >= o) v += u;
    }
    __shared__ int warp_sums[32];
    if (lane == 31) warp_sums[wid] = v;
    __syncthreads();
    if (wid == 0) {
        int wv = warp_sums[lane];
        #pragma unroll
        for (int o = 1; o < 32; o <<= 1) {
            int u = __shfl_up_sync(0xffffffffu, wv, o);
            if (lane >= o) wv += u;
        }
        warp_sums[lane] = wv;
    }
    __syncthreads();
    int excl = v - sum + ((wid > 0) ? warp_sums[wid - 1] : 0);

    int run = excl;
    for (int i = beg; i < end; i++) { ptr[i] = run; run += cnt[i]; }
    if (t == 1023) ptr[n] = run;
}

// ---------------- scatter nnz into both CSR structures ----------------
__global__ void scatter_kernel() {
    int t = blockIdx.x * blockDim.x + threadIdx.x;
    if (t >= NNZ) return;
    int n = g_nidx[t];
    int e = g_eidx[t];
    int p = g_eptr[e] + atomicAdd(&g_efill[e], 1);
    g_enodes[p] = n;
    int q = g_nptr[n] + atomicAdd(&g_nfill[n], 1);
    g_nedges[q] = e;
}

// ------- node -> hyperedge aggregation (fp16 gather, fp32 accum, x4) ---------
__global__ __launch_bounds__(256) void edge_agg_kernel() {
    const int grp  = threadIdx.x >> 6;
    const int lane = threadIdx.x & 63;          // 4 halves per lane
    const int e = blockIdx.x * 4 + grp;
    if (e >= NUM_EDGES) return;
    const int beg = __ldg(&g_eptr[e]);
    const int end = __ldg(&g_eptr[e + 1]);
    const uint2* __restrict__ xl2 = (const uint2*)g_xlh;

    float ax = 0.f, ay = 0.f, az = 0.f, aw = 0.f;
    int j = beg;
    for (; j + 4 <= end; j += 4) {
        const int i0 = __ldg(&g_enodes[j]);
        const int i1 = __ldg(&g_enodes[j + 1]);
        const int i2 = __ldg(&g_enodes[j + 2]);
        const int i3 = __ldg(&g_enodes[j + 3]);
        uint2 u0 = __ldg(&xl2[(size_t)i0 * 64 + lane]);
        uint2 u1 = __ldg(&xl2[(size_t)i1 * 64 + lane]);
        uint2 u2 = __ldg(&xl2[(size_t)i2 * 64 + lane]);
        uint2 u3 = __ldg(&xl2[(size_t)i3 * 64 + lane]);
        float2 p0 = __half22float2(*(__half2*)&u0.x), q0 = __half22float2(*(__half2*)&u0.y);
        float2 p1 = __half22float2(*(__half2*)&u1.x), q1 = __half22float2(*(__half2*)&u1.y);
        float2 p2 = __half22float2(*(__half2*)&u2.x), q2 = __half22float2(*(__half2*)&u2.y);
        float2 p3 = __half22float2(*(__half2*)&u3.x), q3 = __half22float2(*(__half2*)&u3.y);
        ax += (p0.x + p1.x) + (p2.x + p3.x);
        ay += (p0.y + p1.y) + (p2.y + p3.y);
        az += (q0.x + q1.x) + (q2.x + q3.x);
        aw += (q0.y + q1.y) + (q2.y + q3.y);
    }
    for (; j < end; j++) {
        const int i0 = __ldg(&g_enodes[j]);
        uint2 u0 = __ldg(&xl2[(size_t)i0 * 64 + lane]);
        float2 p0 = __half22float2(*(__half2*)&u0.x), q0 = __half22float2(*(__half2*)&u0.y);
        ax += p0.x; ay += p0.y; az += q0.x; aw += q0.y;
    }
    const float card = (float)(end - beg);
    const float binv = (card > 0.f) ? (1.f / card) : 0.f;
    uint2 o;
    *(__half2*)&o.x = __floats2half2_rn(ax * binv, ay * binv);
    *(__half2*)&o.y = __floats2half2_rn(az * binv, aw * binv);
    ((uint2*)g_efh)[(size_t)e * 64 + lane] = o;
}

// -- hyperedge -> node aggregation + bias; D from CSR; fp16 gather, fp32 out --
__global__ __launch_bounds__(256) void node_agg_kernel(float* __restrict__ out,
                                                       const float* __restrict__ b,
                                                       const float* __restrict__ w) {
    const int grp  = threadIdx.x >> 6;
    const int lane = threadIdx.x & 63;
    const int n = blockIdx.x * 4 + grp;
    if (n >= NUM_NODES) return;
    const int beg = __ldg(&g_nptr[n]);
    const int end = __ldg(&g_nptr[n + 1]);
    const uint2* __restrict__ ef2 = (const uint2*)g_efh;

    float ax = 0.f, ay = 0.f, az = 0.f, aw = 0.f;
    float dsum = 0.f;
    int j = beg;
    for (; j + 4 <= end; j += 4) {
        const int e0 = __ldg(&g_nedges[j]);
        const int e1 = __ldg(&g_nedges[j + 1]);
        const int e2 = __ldg(&g_nedges[j + 2]);
        const int e3 = __ldg(&g_nedges[j + 3]);
        uint2 u0 = __ldg(&ef2[(size_t)e0 * 64 + lane]);
        uint2 u1 = __ldg(&ef2[(size_t)e1 * 64 + lane]);
        uint2 u2 = __ldg(&ef2[(size_t)e2 * 64 + lane]);
        uint2 u3 = __ldg(&ef2[(size_t)e3 * 64 + lane]);
        dsum += (__ldg(&w[e0]) + __ldg(&w[e1])) + (__ldg(&w[e2]) + __ldg(&w[e3]));
        float2 p0 = __half22float2(*(__half2*)&u0.x), q0 = __half22float2(*(__half2*)&u0.y);
        float2 p1 = __half22float2(*(__half2*)&u1.x), q1 = __half22float2(*(__half2*)&u1.y);
        float2 p2 = __half22float2(*(__half2*)&u2.x), q2 = __half22float2(*(__half2*)&u2.y);
        float2 p3 = __half22float2(*(__half2*)&u3.x), q3 = __half22float2(*(__half2*)&u3.y);
        ax += (p0.x + p1.x) + (p2.x + p3.x);
        ay += (p0.y + p1.y) + (p2.y + p3.y);
        az += (q0.x + q1.x) + (q2.x + q3.x);
        aw += (q0.y + q1.y) + (q2.y + q3.y);
    }
    for (; j < end; j++) {
        const int e0 = __ldg(&g_nedges[j]);
        uint2 u0 = __ldg(&ef2[(size_t)e0 * 64 + lane]);
        dsum += __ldg(&w[e0]);
        float2 p0 = __half22float2(*(__half2*)&u0.x), q0 = __half22float2(*(__half2*)&u0.y);
        ax += p0.x; ay += p0.y; az += q0.x; aw += q0.y;
    }
    const float dinv = (dsum > 0.f) ? (1.f / dsum) : 0.f;
    const float4 bb = __ldg(&((const float4*)b)[lane]);
    ((float4*)out)[(size_t)n * 64 + lane] =
        make_float4(ax * dinv + bb.x, ay * dinv + bb.y,
                    az * dinv + bb.z, aw * dinv + bb.w);
}

// ---------------- launch ----------------
extern "C" void kernel_launch(void* const* d_in, const int* in_sizes, int n_in,
                              void* d_out, int out_size) {
    const float* x  = nullptr;
    const void*  hi = nullptr;
    const float* w  = nullptr;
    const float* W  = nullptr;
    const float* b  = nullptr;
    for (int i = 0; i < n_in; i++) {
        switch (in_sizes[i]) {
            case NUM_NODES * D_IN:   x  = (const float*)d_in[i]; break;
            case 2 * NNZ:            hi = d_in[i];               break;
            case NUM_EDGES:          w  = (const float*)d_in[i]; break;
            case D_IN * D_OUT:       W  = (const float*)d_in[i]; break;
            case D_OUT:              b  = (const float*)d_in[i]; break;
            default: break;
        }
    }
    float* out = (float*)d_out;

    cudaStream_t s1;
    cudaStreamCreate(&s1);
    cudaEvent_t evFork, evJoin;
    cudaEventCreateWithFlags(&evFork, cudaEventDisableTiming);
    cudaEventCreateWithFlags(&evJoin, cudaEventDisableTiming);

    // fork: GEMM chain
    cudaEventRecord(evFork, 0);
    cudaStreamWaitEvent(s1, evFork, 0);
    conv_w_kernel<<<(D_IN * D_OUT + 255) / 256, 256, 0, s1>>>(W);
    dim3 ggrid(D_OUT / 128, (NUM_NODES + 127) / 128);
    mma_gemm_kernel<<<ggrid, 256, 0, s1>>>(x);
    cudaEventRecord(evJoin, s1);

    // main stream: CSR build chain
    probe_kernel<<<1, 256>>>((const unsigned int*)hi);
    zero_kernel<<<(NUM_NODES + 255) / 256, 256>>>();
    decode_count_kernel<<<(NNZ + 255) / 256, 256>>>(hi);
    scan_kernel<<<2, 1024>>>();
    scatter_kernel<<<(NNZ + 255) / 256, 256>>>();

    // join: aggregations need both chains
    cudaStreamWaitEvent(0, evJoin, 0);
    edge_agg_kernel<<<(NUM_EDGES + 3) / 4, 256>>>();
    node_agg_kernel<<<(NUM_NODES + 3) / 4, 256>>>(out, b, w);
}

// round 15
// speedup vs baseline: 2.6769x; 1.0502x over previous
#include <cuda_runtime.h>
#include <cuda_fp16.h>
#include <cstdint>

#define NUM_NODES 50000
#define NUM_EDGES 50000
#define NNZ       500000
#define D_IN      256
#define D_OUT     256

// ---------------- static device scratch (no allocation allowed) ----------------
__device__ __half g_xlh[(size_t)NUM_NODES * D_OUT];    // x @ W (fp16 storage)
__device__ __half g_efh[(size_t)NUM_EDGES * D_OUT];    // per-hyperedge feats (fp16)
__device__ int   g_ecnt[NUM_EDGES];
__device__ int   g_ncnt[NUM_NODES];
__device__ int   g_eptr[NUM_EDGES + 1];
__device__ int   g_nptr[NUM_NODES + 1];
__device__ int   g_efill[NUM_EDGES];
__device__ int   g_nfill[NUM_NODES];
__device__ int   g_enodes[NNZ];
__device__ int   g_nedges[NNZ];
__device__ int   g_nidx[NNZ];
__device__ int   g_eidx[NNZ];
__device__ int   g_is64;
// fp16 W for HMMA GEMM
__device__ __half g_wh[D_IN * D_OUT];                  // stored [N][K] (K-major)

// ---------------- helpers ----------------
__device__ __forceinline__ uint32_t smem_to_u32(const void* p) {
    uint32_t a;
    asm("{ .reg .u64 t; cvta.to.shared.u64 t, %1; cvt.u32.u64 %0, t; }" : "=r"(a) : "l"(p));
    return a;
}
#define LDMATRIX_X4(r, addr) \
    asm volatile("ldmatrix.sync.aligned.m8n8.x4.shared.b16 {%0,%1,%2,%3}, [%4];" \
                 : "=r"((r)[0]), "=r"((r)[1]), "=r"((r)[2]), "=r"((r)[3]) : "r"(addr))
__device__ __forceinline__ void mma16816(float* d, const uint32_t* a, const uint32_t* b) {
    asm volatile("mma.sync.aligned.m16n8k16.row.col.f32.f16.f16.f32 "
                 "{%0,%1,%2,%3}, {%4,%5,%6,%7}, {%8,%9}, {%0,%1,%2,%3};"
                 : "+f"(d[0]), "+f"(d[1]), "+f"(d[2]), "+f"(d[3])
                 : "r"(a[0]), "r"(a[1]), "r"(a[2]), "r"(a[3]), "r"(b[0]), "r"(b[1]));
}
// 4 fp32 -> 2 packed f16x2
__device__ __forceinline__ void cvt4h(const float4 v, uint32_t* hi2) {
    __half2 H0 = __floats2half2_rn(v.x, v.y);
    __half2 H1 = __floats2half2_rn(v.z, v.w);
    hi2[0] = *(uint32_t*)&H0; hi2[1] = *(uint32_t*)&H1;
}

// ---------------- probe index dtype (int64 vs int32) ----------------
__global__ void probe_kernel(const unsigned int* __restrict__ buf) {
    __shared__ int found_nonzero;
    if (threadIdx.x == 0) found_nonzero = 0;
    __syncthreads();
    for (int i = threadIdx.x; i < 512; i += blockDim.x)
        if (buf[2 * i + 1] != 0u) atomicExch(&found_nonzero, 1);
    __syncthreads();
    if (threadIdx.x == 0) g_is64 = found_nonzero ? 0 : 1;
}

// ---------------- zero counters ----------------
__global__ void zero_kernel() {
    int t = blockIdx.x * blockDim.x + threadIdx.x;
    if (t < NUM_NODES) { g_ncnt[t] = 0; g_nfill[t] = 0; }
    if (t < NUM_EDGES) { g_ecnt[t] = 0; g_efill[t] = 0; }
}

// ---------------- decode indices + histograms (fused) ----------------
__global__ void decode_count_kernel(const void* __restrict__ buf) {
    int t = blockIdx.x * blockDim.x + threadIdx.x;
    if (t >= NNZ) return;
    int n, e;
    if (g_is64) {
        const long long* p = (const long long*)buf;
        n = (int)p[t];
        e = (int)p[NNZ + t];
    } else {
        const int* p = (const int*)buf;
        n = p[t];
        e = p[NNZ + t];
    }
    if ((unsigned)n >= NUM_NODES) n = 0;
    if ((unsigned)e >= NUM_EDGES) e = 0;
    g_nidx[t] = n;
    g_eidx[t] = e;
    atomicAdd(&g_ecnt[e], 1);
    atomicAdd(&g_ncnt[n], 1);
}

// W[k][n] -> fp16, stored [n][k] (K-major B for row.col mma)
__global__ void conv_w_kernel(const float* __restrict__ W) {
    int t = blockIdx.x * blockDim.x + threadIdx.x;
    if (t >= D_IN * D_OUT) return;
    int n = t >> 8, k = t & 255;
    g_wh[n * D_IN + k] = __float2half_rn(__ldg(&W[k * D_OUT + n]));
}

// ---------------- HMMA fp16 GEMM: g_xlh = x @ W (single pass) ----------------
#define SPAD 40
__global__ __launch_bounds__(256, 2) void mma_gemm_kernel(const float* __restrict__ X) {
    __shared__ __half As[128][SPAD];
    __shared__ __half Bs[128][SPAD];

    const int tid  = threadIdx.x;
    const int lane = tid & 31;
    const int wid  = tid >> 5;
    const int wm   = (wid >> 1) * 32;
    const int wn   = (wid & 1) * 64;
    const int m0   = blockIdx.y * 128;
    const int n0   = blockIdx.x * 128;

    float acc[2][8][4];
    #pragma unroll
    for (int i = 0; i < 2; i++)
        #pragma unroll
        for (int j = 0; j < 8; j++)
            #pragma unroll
            for (int q = 0; q < 4; q++) acc[i][j][q] = 0.f;

    const uint32_t a_b = smem_to_u32(&As[0][0]);
    const uint32_t b_b = smem_to_u32(&Bs[0][0]);

    for (int kc = 0; kc < 8; kc++) {
        const int k0 = kc * 32;
        __syncthreads();
        #pragma unroll
        for (int i = tid; i < 512; i += 256) {
            const int r = i >> 2, seg = i & 3;
            const int gr = m0 + r;
            float4 v0 = make_float4(0.f, 0.f, 0.f, 0.f), v1 = v0;
            if (gr < NUM_NODES) {
                const float* src = X + (size_t)gr * D_IN + k0 + seg * 8;
                v0 = __ldg((const float4*)src);
                v1 = __ldg((const float4*)(src + 4));
            }
            uint32_t hi[4];
            cvt4h(v0, hi);
            cvt4h(v1, hi + 2);
            *(uint4*)&As[r][seg * 8] = make_uint4(hi[0], hi[1], hi[2], hi[3]);
            const int gn = n0 + r;
            *(uint4*)&Bs[r][seg * 8] = *(const uint4*)(g_wh + (size_t)gn * D_IN + k0 + seg * 8);
        }
        __syncthreads();

        #pragma unroll
        for (int kk = 0; kk < 32; kk += 16) {
            uint32_t ah[2][4];
            #pragma unroll
            for (int ti = 0; ti < 2; ti++) {
                const int row = wm + ti * 16 + (lane & 15);
                const uint32_t off = (uint32_t)(row * (SPAD * 2) + (kk + (lane >> 4) * 8) * 2);
                LDMATRIX_X4(ah[ti], a_b + off);
            }
            uint32_t bh[8][2];
            #pragma unroll
            for (int tj = 0; tj < 4; tj++) {
                const int row = wn + tj * 16 + (lane & 15);
                const uint32_t off = (uint32_t)(row * (SPAD * 2) + (kk + (lane >> 4) * 8) * 2);
                uint32_t r4[4];
                LDMATRIX_X4(r4, b_b + off);
                bh[2 * tj][0] = r4[0]; bh[2 * tj + 1][0] = r4[1];
                bh[2 * tj][1] = r4[2]; bh[2 * tj + 1][1] = r4[3];
            }
            #pragma unroll
            for (int ti = 0; ti < 2; ti++)
                #pragma unroll
                for (int j = 0; j < 8; j++)
                    mma16816(acc[ti][j], ah[ti], bh[j]);
        }
    }

    #pragma unroll
    for (int ti = 0; ti < 2; ti++) {
        const int r0 = m0 + wm + ti * 16 + (lane >> 2);
        #pragma unroll
        for (int j = 0; j < 8; j++) {
            const int c = n0 + wn + j * 8 + (lane & 3) * 2;
            if (r0 < NUM_NODES)
                *(__half2*)&g_xlh[(size_t)r0 * D_OUT + c] =
                    __floats2half2_rn(acc[ti][j][0], acc[ti][j][1]);
            if (r0 + 8 < NUM_NODES)
                *(__half2*)&g_xlh[(size_t)(r0 + 8) * D_OUT + c] =
                    __floats2half2_rn(acc[ti][j][2], acc[ti][j][3]);
        }
    }
}

// ---------------- exclusive scan (2 blocks; thread-sequential + shuffle scan) --
__global__ __launch_bounds__(1024) void scan_kernel() {
    const int* cnt = (blockIdx.x == 0) ? g_ecnt : g_ncnt;
    int* ptr       = (blockIdx.x == 0) ? g_eptr : g_nptr;
    const int n    = (blockIdx.x == 0) ? NUM_EDGES : NUM_NODES;
    const int IPT  = (n + 1023) / 1024;

    const int t    = threadIdx.x;
    const int lane = t & 31;
    const int wid  = t >> 5;
    int beg = t * IPT; if (beg > n) beg = n;
    int end = beg + IPT; if (end > n) end = n;

    int sum = 0;
    for (int i = beg; i < end; i++) sum += cnt[i];

    int v = sum;
    #pragma unroll
    for (int o = 1; o < 32; o <<= 1) {
        int u = __shfl_up_sync(0xffffffffu, v, o);
        if (lane >= o) v += u;
    }
    __shared__ int warp_sums[32];
    if (lane == 31) warp_sums[wid] = v;
    __syncthreads();
    if (wid == 0) {
        int wv = warp_sums[lane];
        #pragma unroll
        for (int o = 1; o < 32; o <<= 1) {
            int u = __shfl_up_sync(0xffffffffu, wv, o);
            if (lane >= o) wv += u;
        }
        warp_sums[lane] = wv;
    }
    __syncthreads();
    int excl = v - sum + ((wid > 0) ? warp_sums[wid - 1] : 0);

    int run = excl;
    for (int i = beg; i < end; i++) { ptr[i] = run; run += cnt[i]; }
    if (t == 1023) ptr[n] = run;
}

// ---------------- scatter nnz into both CSR structures ----------------
__global__ void scatter_kernel() {
    int t = blockIdx.x * blockDim.x + threadIdx.x;
    if (t >= NNZ) return;
    int n = g_nidx[t];
    int e = g_eidx[t];
    int p = g_eptr[e] + atomicAdd(&g_efill[e], 1);
    g_enodes[p] = n;
    int q = g_nptr[n] + atomicAdd(&g_nfill[n], 1);
    g_nedges[q] = e;
}

// ------- node -> hyperedge aggregation (fp16 gather, fp32 accum, x8) ---------
__global__ __launch_bounds__(256) void edge_agg_kernel() {
    const int grp  = threadIdx.x >> 6;
    const int lane = threadIdx.x & 63;          // 4 halves per lane
    const int e = blockIdx.x * 4 + grp;
    if (e >= NUM_EDGES) return;
    const int beg = __ldg(&g_eptr[e]);
    const int end = __ldg(&g_eptr[e + 1]);
    const uint2* __restrict__ xl2 = (const uint2*)g_xlh;

    float ax = 0.f, ay = 0.f, az = 0.f, aw = 0.f;
    int j = beg;
    for (; j + 8 <= end; j += 8) {
        int idx[8];
        #pragma unroll
        for (int u = 0; u < 8; u++) idx[u] = __ldg(&g_enodes[j + u]);
        uint2 uu[8];
        #pragma unroll
        for (int u = 0; u < 8; u++) uu[u] = __ldg(&xl2[(size_t)idx[u] * 64 + lane]);
        #pragma unroll
        for (int u = 0; u < 8; u++) {
            float2 p = __half22float2(*(__half2*)&uu[u].x);
            float2 q = __half22float2(*(__half2*)&uu[u].y);
            ax += p.x; ay += p.y; az += q.x; aw += q.y;
        }
    }
    for (; j < end; j++) {
        const int i0 = __ldg(&g_enodes[j]);
        uint2 u0 = __ldg(&xl2[(size_t)i0 * 64 + lane]);
        float2 p0 = __half22float2(*(__half2*)&u0.x), q0 = __half22float2(*(__half2*)&u0.y);
        ax += p0.x; ay += p0.y; az += q0.x; aw += q0.y;
    }
    const float card = (float)(end - beg);
    const float binv = (card > 0.f) ? (1.f / card) : 0.f;
    uint2 o;
    *(__half2*)&o.x = __floats2half2_rn(ax * binv, ay * binv);
    *(__half2*)&o.y = __floats2half2_rn(az * binv, aw * binv);
    ((uint2*)g_efh)[(size_t)e * 64 + lane] = o;
}

// -- hyperedge -> node aggregation + bias; D from CSR; fp16 gather, x8 --------
__global__ __launch_bounds__(256) void node_agg_kernel(float* __restrict__ out,
                                                       const float* __restrict__ b,
                                                       const float* __restrict__ w) {
    const int grp  = threadIdx.x >> 6;
    const int lane = threadIdx.x & 63;
    const int n = blockIdx.x * 4 + grp;
    if (n >= NUM_NODES) return;
    const int beg = __ldg(&g_nptr[n]);
    const int end = __ldg(&g_nptr[n + 1]);
    const uint2* __restrict__ ef2 = (const uint2*)g_efh;

    float ax = 0.f, ay = 0.f, az = 0.f, aw = 0.f;
    float dsum = 0.f;
    int j = beg;
    for (; j + 8 <= end; j += 8) {
        int idx[8];
        #pragma unroll
        for (int u = 0; u < 8; u++) idx[u] = __ldg(&g_nedges[j + u]);
        uint2 uu[8];
        #pragma unroll
        for (int u = 0; u < 8; u++) uu[u] = __ldg(&ef2[(size_t)idx[u] * 64 + lane]);
        #pragma unroll
        for (int u = 0; u < 8; u++) dsum += __ldg(&w[idx[u]]);
        #pragma unroll
        for (int u = 0; u < 8; u++) {
            float2 p = __half22float2(*(__half2*)&uu[u].x);
            float2 q = __half22float2(*(__half2*)&uu[u].y);
            ax += p.x; ay += p.y; az += q.x; aw += q.y;
        }
    }
    for (; j < end; j++) {
        const int e0 = __ldg(&g_nedges[j]);
        uint2 u0 = __ldg(&ef2[(size_t)e0 * 64 + lane]);
        dsum += __ldg(&w[e0]);
        float2 p0 = __half22float2(*(__half2*)&u0.x), q0 = __half22float2(*(__half2*)&u0.y);
        ax += p0.x; ay += p0.y; az += q0.x; aw += q0.y;
    }
    const float dinv = (dsum > 0.f) ? (1.f / dsum) : 0.f;
    const float4 bb = __ldg(&((const float4*)b)[lane]);
    ((float4*)out)[(size_t)n * 64 + lane] =
        make_float4(ax * dinv + bb.x, ay * dinv + bb.y,
                    az * dinv + bb.z, aw * dinv + bb.w);
}

// ---------------- launch ----------------
extern "C" void kernel_launch(void* const* d_in, const int* in_sizes, int n_in,
                              void* d_out, int out_size) {
    const float* x  = nullptr;
    const void*  hi = nullptr;
    const float* w  = nullptr;
    const float* W  = nullptr;
    const float* b  = nullptr;
    for (int i = 0; i < n_in; i++) {
        switch (in_sizes[i]) {
            case NUM_NODES * D_IN:   x  = (const float*)d_in[i]; break;
            case 2 * NNZ:            hi = d_in[i];               break;
            case NUM_EDGES:          w  = (const float*)d_in[i]; break;
            case D_IN * D_OUT:       W  = (const float*)d_in[i]; break;
            case D_OUT:              b  = (const float*)d_in[i]; break;
            default: break;
        }
    }
    float* out = (float*)d_out;

    cudaStream_t s1;
    cudaStreamCreate(&s1);
    cudaEvent_t evFork, evJoin;
    cudaEventCreateWithFlags(&evFork, cudaEventDisableTiming);
    cudaEventCreateWithFlags(&evJoin, cudaEventDisableTiming);

    // fork: GEMM chain
    cudaEventRecord(evFork, 0);
    cudaStreamWaitEvent(s1, evFork, 0);
    conv_w_kernel<<<(D_IN * D_OUT + 255) / 256, 256, 0, s1>>>(W);
    dim3 ggrid(D_OUT / 128, (NUM_NODES + 127) / 128);
    mma_gemm_kernel<<<ggrid, 256, 0, s1>>>(x);
    cudaEventRecord(evJoin, s1);

    // main stream: CSR build chain
    probe_kernel<<<1, 256>>>((const unsigned int*)hi);
    zero_kernel<<<(NUM_NODES + 255) / 256, 256>>>();
    decode_count_kernel<<<(NNZ + 255) / 256, 256>>>(hi);
    scan_kernel<<<2, 1024>>>();
    scatter_kernel<<<(NNZ + 255) / 256, 256>>>();

    // join: aggregations need both chains
    cudaStreamWaitEvent(0, evJoin, 0);
    edge_agg_kernel<<<(NUM_EDGES + 3) / 4, 256>>>();
    node_agg_kernel<<<(NUM_NODES + 3) / 4, 256>>>(out, b, w);
}